// round 6
// baseline (speedup 1.0000x reference)
#include <cuda_runtime.h>
#include <cuda_bf16.h>
#include <cstdint>

#define B_   2
#define S_   2048
#define D_   1024
#define H_   16
#define HD_  64
#define M_   (B_ * S_)   // 4096
#define GN   D_
#define GK   D_

// ---------------- scratch (__device__ globals; no allocs allowed) ----------
__device__ __align__(128) int8_t g_A12[M_ * 16 * 128];     // X 2-term int8
__device__ __align__(128) int8_t g_W12[3][GN * 16 * 128];  // Wq/Wk/Wv int8 [N][K]
__device__ __nv_bfloat16 g_Ahi[M_ * GK];                   // ctx hi/lo (Wo input)
__device__ __nv_bfloat16 g_Alo[M_ * GK];
__device__ __nv_bfloat16 g_Whi[GK * GN];                   // Wo bf16 [N][K]
__device__ __nv_bfloat16 g_Wlo[GK * GN];
__device__ __nv_bfloat16 g_Qh[M_ * D_], g_Ql[M_ * D_];
__device__ __nv_bfloat16 g_Kh[M_ * D_], g_Kl[M_ * D_];
__device__ __nv_bfloat16 g_Vh[M_ * D_], g_Vl[M_ * D_];
__device__ float g_amax[4];   // 0:X  1..3:Wq,Wk,Wv

// ---------------- PTX helpers (sm_80+ only) --------------------------------
__device__ __forceinline__ uint32_t smem_u32(const void* p) {
    uint32_t a;
    asm("{ .reg .u64 t; cvta.to.shared.u64 t, %1; cvt.u32.u64 %0, t; }"
        : "=r"(a) : "l"(p));
    return a;
}
#define SW(o) ((o) ^ (((o) >> 3) & 0x70))
__device__ __forceinline__ void cp16(uint32_t d, const void* g) {
    asm volatile("cp.async.cg.shared.global [%0], [%1], 16;" :: "r"(d), "l"(g) : "memory");
}
#define CP_COMMIT() asm volatile("cp.async.commit_group;" ::: "memory")
#define CP_WAIT1()  asm volatile("cp.async.wait_group 1;" ::: "memory")
#define CP_WAIT2()  asm volatile("cp.async.wait_group 2;" ::: "memory")

__device__ __forceinline__ void ldsm4(uint32_t& r0, uint32_t& r1,
                                      uint32_t& r2, uint32_t& r3, uint32_t a) {
    asm volatile("ldmatrix.sync.aligned.m8n8.x4.shared.b16 {%0,%1,%2,%3}, [%4];"
                 : "=r"(r0), "=r"(r1), "=r"(r2), "=r"(r3) : "r"(a));
}
__device__ __forceinline__ void ldsm4t(uint32_t* r, uint32_t a) {
    asm volatile("ldmatrix.sync.aligned.m8n8.x4.trans.shared.b16 {%0,%1,%2,%3}, [%4];"
                 : "=r"(r[0]), "=r"(r[1]), "=r"(r[2]), "=r"(r[3]) : "r"(a));
}
__device__ __forceinline__ void mma_bf16(float* c, const uint32_t* a,
                                         uint32_t b0, uint32_t b1) {
    asm volatile(
        "mma.sync.aligned.m16n8k16.row.col.f32.bf16.bf16.f32 "
        "{%0,%1,%2,%3}, {%4,%5,%6,%7}, {%8,%9}, {%0,%1,%2,%3};"
        : "+f"(c[0]), "+f"(c[1]), "+f"(c[2]), "+f"(c[3])
        : "r"(a[0]), "r"(a[1]), "r"(a[2]), "r"(a[3]), "r"(b0), "r"(b1));
}
__device__ __forceinline__ void mma_s8(int* c, const uint32_t* a,
                                       uint32_t b0, uint32_t b1) {
    asm volatile(
        "mma.sync.aligned.m16n8k32.row.col.s32.s8.s8.s32 "
        "{%0,%1,%2,%3}, {%4,%5,%6,%7}, {%8,%9}, {%0,%1,%2,%3};"
        : "+r"(c[0]), "+r"(c[1]), "+r"(c[2]), "+r"(c[3])
        : "r"(a[0]), "r"(a[1]), "r"(a[2]), "r"(a[3]), "r"(b0), "r"(b1));
}
__device__ __forceinline__ uint32_t pack_bf2(float a, float b) {
    uint32_t d;
    asm("cvt.rn.bf16x2.f32 %0, %1, %2;" : "=r"(d) : "f"(b), "f"(a));
    return d;
}
__device__ __forceinline__ float trunc_split(float v, uint32_t& hi_bits) {
    hi_bits = __float_as_uint(v) & 0xffff0000u;
    return v - __uint_as_float(hi_bits);
}

// ---------------- amax + quantization ---------------------------------------
__global__ void reset_amax() { if (threadIdx.x < 4) g_amax[threadIdx.x] = 0.0f; }

__global__ __launch_bounds__(256) void amax_k(const float* __restrict__ x,
                                              float* __restrict__ out, int n4) {
    float m = 0.0f;
    for (int i = blockIdx.x * 256 + threadIdx.x; i < n4; i += gridDim.x * 256) {
        float4 v = ((const float4*)x)[i];
        m = fmaxf(m, fmaxf(fmaxf(fabsf(v.x), fabsf(v.y)),
                           fmaxf(fabsf(v.z), fabsf(v.w))));
    }
#pragma unroll
    for (int o = 16; o; o >>= 1)
        m = fmaxf(m, __shfl_xor_sync(0xffffffffu, m, o));
    if ((threadIdx.x & 31) == 0)
        atomicMax((unsigned int*)out, __float_as_uint(m));
}

__device__ __forceinline__ int q8v(float x, float inv) {
    float f = rintf(x * inv);
    return (int)fminf(127.0f, fmaxf(-127.0f, f));
}

// X [M][K] f32 -> 2-term int8, layout ((m*16+c)*128 + k%64), term2 at +64
__global__ __launch_bounds__(256) void quant_act(
    const float* __restrict__ X, int8_t* __restrict__ A12,
    const float* __restrict__ amp) {
    const int t = blockIdx.x * 256 + threadIdx.x;      // M*K/16 threads
    const int m = t >> 6, k0 = (t & 63) << 4;
    const float amax = *amp;
    const float inv1 = 127.0f / amax, s1 = amax * (1.0f / 127.0f);
    const float inv2 = 254.0f / s1;
    uint32_t u1[4], u2[4];
#pragma unroll
    for (int q = 0; q < 4; q++) {
        float4 v = ((const float4*)X)[(m << 8) + (k0 >> 2) + q];
        float xs[4] = {v.x, v.y, v.z, v.w};
        uint32_t p1 = 0, p2 = 0;
#pragma unroll
        for (int j = 0; j < 4; j++) {
            int a1 = q8v(xs[j], inv1);
            int a2 = q8v(xs[j] - (float)a1 * s1, inv2);
            p1 |= ((uint32_t)a1 & 0xffu) << (j * 8);
            p2 |= ((uint32_t)a2 & 0xffu) << (j * 8);
        }
        u1[q] = p1; u2[q] = p2;
    }
    const size_t base = ((size_t)m * 16 + (k0 >> 6)) * 128 + (k0 & 63);
    *(uint4*)(A12 + base)      = make_uint4(u1[0], u1[1], u1[2], u1[3]);
    *(uint4*)(A12 + base + 64) = make_uint4(u2[0], u2[1], u2[2], u2[3]);
}

// W [K][N] f32 -> transposed 2-term int8 [N][K]
__global__ __launch_bounds__(256) void tquant_w(
    const float* __restrict__ W, int8_t* __restrict__ W12,
    const float* __restrict__ amp) {
    __shared__ float t[32][33];
    const float amax = *amp;
    const float inv1 = 127.0f / amax, s1 = amax * (1.0f / 127.0f);
    const float inv2 = 254.0f / s1;
    const int n0 = blockIdx.x * 32, k0 = blockIdx.y * 32;
    const int tx = threadIdx.x, ty = threadIdx.y;
#pragma unroll
    for (int i = 0; i < 32; i += 8)
        t[ty + i][tx] = W[(size_t)(k0 + ty + i) * GN + n0 + tx];
    __syncthreads();
#pragma unroll
    for (int i = 0; i < 32; i += 8) {
        float v = t[tx][ty + i];
        int a1 = q8v(v, inv1);
        int a2 = q8v(v - (float)a1 * s1, inv2);
        const int n = n0 + ty + i, k = k0 + tx;
        const size_t off = ((size_t)n * 16 + (k >> 6)) * 128 + (k & 63);
        W12[off] = (int8_t)a1;
        W12[off + 64] = (int8_t)a2;
    }
}

// Wo [K][N] f32 -> bf16 hi/lo [N][K]
__global__ __launch_bounds__(256) void transpose_split_w(
    const float* __restrict__ W, __nv_bfloat16* __restrict__ whi,
    __nv_bfloat16* __restrict__ wlo) {
    __shared__ float t[32][33];
    const int n0 = blockIdx.x * 32, k0 = blockIdx.y * 32;
    const int tx = threadIdx.x, ty = threadIdx.y;
#pragma unroll
    for (int i = 0; i < 32; i += 8)
        t[ty + i][tx] = W[(size_t)(k0 + ty + i) * GN + n0 + tx];
    __syncthreads();
#pragma unroll
    for (int i = 0; i < 32; i += 8) {
        float v = t[tx][ty + i];
        uint32_t hb;
        float l = trunc_split(v, hb);
        size_t off = (size_t)(n0 + ty + i) * GK + k0 + tx;
        whi[off] = __ushort_as_bfloat16((unsigned short)(hb >> 16));
        wlo[off] = __float2bfloat16(l);
    }
}

// ---------------- INT8 fused QKV GEMM (grid.z = 0/1/2) ----------------------
// C = sa*sw*(A1W1 + (A1W2+A2W1)/254) + bias, 128x128 tile, bf16 hi/lo out
struct OutP {
    const float *bq, *bk, *bv;
    __nv_bfloat16 *qh, *ql, *kh, *kl, *vh, *vl;
};

#define S8_LOAD(c) do {                                                       \
    uint32_t st_ = sb + ((c) % 3) * 32768;                                    \
    _Pragma("unroll")                                                         \
    for (int i_ = 0; i_ < 4; i_++) {                                          \
        int idx_ = tid + i_ * 256;                                            \
        int r_ = idx_ >> 3, u_ = idx_ & 7;                                    \
        uint32_t so_ = SW((uint32_t)(r_ * 128 + u_ * 16));                    \
        cp16(st_ + so_,         A12 + ((size_t)(m0 + r_) * 16 + (c)) * 128 + u_ * 16); \
        cp16(st_ + 16384 + so_, W12 + ((size_t)(n0 + r_) * 16 + (c)) * 128 + u_ * 16); \
    }                                                                         \
} while (0)

__global__ __launch_bounds__(256) void gemm_s8(
    const int8_t* __restrict__ A12, const int8_t* __restrict__ W12base,
    const float* __restrict__ am, OutP op)
{
    extern __shared__ char smc[];
    const uint32_t sb = smem_u32(smc);
    const int tid = threadIdx.x, lane = tid & 31, wid = tid >> 5;
    const int m0 = blockIdx.y * 128, n0 = blockIdx.x * 128;
    const int z = blockIdx.z;
    const int8_t* W12 = W12base + (size_t)z * (GN * 16 * 128);
    const int wm = (wid & 3) * 32, wn = (wid >> 2) * 64;

    int acc0[2][8][4], acc1[2][8][4];
#pragma unroll
    for (int mi = 0; mi < 2; mi++)
#pragma unroll
        for (int ni = 0; ni < 8; ni++)
#pragma unroll
            for (int r = 0; r < 4; r++) { acc0[mi][ni][r] = 0; acc1[mi][ni][r] = 0; }

    uint32_t arow[2];
#pragma unroll
    for (int mi = 0; mi < 2; mi++)
        arow[mi] = (uint32_t)((wm + mi * 16 + (lane & 15)) * 128 + ((lane >> 4) << 4));
    const uint32_t bno = (uint32_t)((wn + (lane & 7) + ((lane >> 4) << 3)) * 128
                        + (((lane >> 3) & 1) << 4));

    S8_LOAD(0); CP_COMMIT();
    S8_LOAD(1); CP_COMMIT();

    for (int c = 0; c < 16; c++) {
        if (c + 2 < 16) S8_LOAD(c + 2);
        CP_COMMIT();
        CP_WAIT2();
        __syncthreads();
        const uint32_t sa_ = sb + (c % 3) * 32768;
        const uint32_t sw_ = sa_ + 16384;
#pragma unroll
        for (int st2 = 0; st2 < 2; st2++) {
            const uint32_t kb = st2 * 32;
            uint32_t a1[2][4], a2[2][4], w[4][4];
            ldsm4(a1[0][0], a1[0][1], a1[0][2], a1[0][3], sa_ + SW(arow[0] + kb));
            ldsm4(a1[1][0], a1[1][1], a1[1][2], a1[1][3], sa_ + SW(arow[1] + kb));
            ldsm4(a2[0][0], a2[0][1], a2[0][2], a2[0][3], sa_ + SW(arow[0] + kb + 64));
            ldsm4(a2[1][0], a2[1][1], a2[1][2], a2[1][3], sa_ + SW(arow[1] + kb + 64));
#pragma unroll
            for (int nt = 0; nt < 4; nt++)
                ldsm4(w[nt][0], w[nt][1], w[nt][2], w[nt][3],
                      sw_ + SW(bno + nt * 2048 + kb));
#pragma unroll
            for (int mi = 0; mi < 2; mi++)
#pragma unroll
                for (int ni = 0; ni < 8; ni++) {
                    mma_s8(acc0[mi][ni], a1[mi],
                           w[ni >> 1][(ni & 1) * 2], w[ni >> 1][(ni & 1) * 2 + 1]);
                    mma_s8(acc1[mi][ni], a2[mi],
                           w[ni >> 1][(ni & 1) * 2], w[ni >> 1][(ni & 1) * 2 + 1]);
                }
#pragma unroll
            for (int nt = 0; nt < 4; nt++)
                ldsm4(w[nt][0], w[nt][1], w[nt][2], w[nt][3],
                      sw_ + SW(bno + nt * 2048 + kb + 64));
#pragma unroll
            for (int mi = 0; mi < 2; mi++)
#pragma unroll
                for (int ni = 0; ni < 8; ni++)
                    mma_s8(acc1[mi][ni], a1[mi],
                           w[ni >> 1][(ni & 1) * 2], w[ni >> 1][(ni & 1) * 2 + 1]);
        }
        __syncthreads();
    }

    const float sc = (am[0] * (1.0f / 127.0f)) * (am[1 + z] * (1.0f / 127.0f));
    const float* bias = (z == 0) ? op.bq : (z == 1) ? op.bk : op.bv;
    __nv_bfloat16* oh = (z == 0) ? op.qh : (z == 1) ? op.kh : op.vh;
    __nv_bfloat16* ol = (z == 0) ? op.ql : (z == 1) ? op.kl : op.vl;
    const int r0 = lane >> 2, cq = (lane & 3) * 2;
#pragma unroll
    for (int mi = 0; mi < 2; mi++) {
#pragma unroll
        for (int ni = 0; ni < 8; ni++) {
            const int rr = m0 + wm + mi * 16 + r0;
            const int cc = n0 + wn + ni * 8 + cq;
            const float2 bv = *(const float2*)&bias[cc];
            float v0 = sc * ((float)acc0[mi][ni][0] + (float)acc1[mi][ni][0] * (1.0f / 254.0f)) + bv.x;
            float v1 = sc * ((float)acc0[mi][ni][1] + (float)acc1[mi][ni][1] * (1.0f / 254.0f)) + bv.y;
            float v2 = sc * ((float)acc0[mi][ni][2] + (float)acc1[mi][ni][2] * (1.0f / 254.0f)) + bv.x;
            float v3 = sc * ((float)acc0[mi][ni][3] + (float)acc1[mi][ni][3] * (1.0f / 254.0f)) + bv.y;
            const int h = cc >> 6, d = cc & 63;
            const int bb = rr >> 11;
            const int s0 = rr & 2047, s1 = (rr + 8) & 2047;
            const size_t o0 = ((((size_t)bb * H_ + h) * S_ + s0) << 6) + d;
            const size_t o1 = ((((size_t)bb * H_ + h) * S_ + s1) << 6) + d;
            uint32_t h0, h1, h2, h3;
            float l0 = trunc_split(v0, h0), l1 = trunc_split(v1, h1);
            float l2 = trunc_split(v2, h2), l3 = trunc_split(v3, h3);
            *(uint32_t*)(oh + o0) = __byte_perm(h0, h1, 0x7632);
            *(uint32_t*)(oh + o1) = __byte_perm(h2, h3, 0x7632);
            *(uint32_t*)(ol + o0) = pack_bf2(l0, l1);
            *(uint32_t*)(ol + o1) = pack_bf2(l2, l3);
        }
    }
}

// ---------------- bf16 3-pass GEMM (Wo only, fp32 out) ----------------------
#define LOAD_CHUNK(c) do {                                                   \
    int ph_ = (c) >> 4, kc_ = ((c) & 15) * 64;                               \
    const __nv_bfloat16* As_ = (ph_ == 2) ? Alo : Ahi;                       \
    const __nv_bfloat16* Bs_ = (ph_ == 1) ? Blo : Bhi;                       \
    uint32_t st_ = sb + ((c) % 3) * 32768;                                   \
    const __nv_bfloat16* ga_ = As_ + (size_t)(m0 + lrow) * GK + kc_ + lhalf * 32; \
    const __nv_bfloat16* gb_ = Bs_ + (size_t)(n0 + lrow) * GK + kc_ + lhalf * 32; \
    uint32_t ob_ = lrow * 128 + lhalf * 64;                                  \
    _Pragma("unroll")                                                        \
    for (int q_ = 0; q_ < 4; q_++) {                                         \
        cp16(st_ + SW(ob_ + q_ * 16), ga_ + q_ * 8);                         \
        cp16(st_ + 16384 + SW(ob_ + q_ * 16), gb_ + q_ * 8);                 \
    }                                                                        \
} while (0)

__global__ __launch_bounds__(256) void gemm_tc(
    const __nv_bfloat16* __restrict__ Ahi, const __nv_bfloat16* __restrict__ Alo,
    const __nv_bfloat16* __restrict__ Bhi, const __nv_bfloat16* __restrict__ Blo,
    const float* __restrict__ bias, float* __restrict__ C)
{
    extern __shared__ char smc[];
    const uint32_t sb = smem_u32(smc);
    const int tid = threadIdx.x, lane = tid & 31, wid = tid >> 5;
    const int m0 = blockIdx.y * 128, n0 = blockIdx.x * 128;
    const int wm = (wid & 3) * 32, wn = (wid >> 2) * 64;
    const int lrow = tid >> 1, lhalf = tid & 1;

    float acc[2][8][4];
#pragma unroll
    for (int mi = 0; mi < 2; mi++)
#pragma unroll
        for (int ni = 0; ni < 8; ni++)
#pragma unroll
            for (int r = 0; r < 4; r++) acc[mi][ni][r] = 0.0f;

    uint32_t aoff[2], boff[4];
#pragma unroll
    for (int mi = 0; mi < 2; mi++)
        aoff[mi] = (wm + mi * 16 + (lane & 15)) * 128 + ((lane >> 4) << 4);
#pragma unroll
    for (int nt = 0; nt < 4; nt++)
        boff[nt] = (wn + nt * 16 + (lane & 7) + ((lane >> 4) << 3)) * 128
                 + (((lane >> 3) & 1) << 4);

    LOAD_CHUNK(0); CP_COMMIT();
    LOAD_CHUNK(1); CP_COMMIT();

    for (int c = 0; c < 48; c++) {
        if (c + 2 < 48) LOAD_CHUNK(c + 2);
        CP_COMMIT();
        CP_WAIT2();
        __syncthreads();
        const uint32_t sa = sb + (c % 3) * 32768;
        const uint32_t sB = sa + 16384;
#pragma unroll
        for (int k16 = 0; k16 < 4; k16++) {
            const uint32_t kb = k16 * 32;
            uint32_t a[2][4], bf[4][4];
            ldsm4(a[0][0], a[0][1], a[0][2], a[0][3], sa + SW(aoff[0] + kb));
            ldsm4(a[1][0], a[1][1], a[1][2], a[1][3], sa + SW(aoff[1] + kb));
#pragma unroll
            for (int nt = 0; nt < 4; nt++)
                ldsm4(bf[nt][0], bf[nt][1], bf[nt][2], bf[nt][3],
                      sB + SW(boff[nt] + kb));
#pragma unroll
            for (int mi = 0; mi < 2; mi++)
#pragma unroll
                for (int ni = 0; ni < 8; ni++)
                    mma_bf16(acc[mi][ni], a[mi],
                             bf[ni >> 1][(ni & 1) * 2], bf[ni >> 1][(ni & 1) * 2 + 1]);
        }
        __syncthreads();
    }

    const int r0 = lane >> 2, cq = (lane & 3) * 2;
#pragma unroll
    for (int mi = 0; mi < 2; mi++) {
#pragma unroll
        for (int ni = 0; ni < 8; ni++) {
            const int rr = m0 + wm + mi * 16 + r0;
            const int cc = n0 + wn + ni * 8 + cq;
            const float2 bv = *(const float2*)&bias[cc];
            *(float2*)&C[(size_t)rr * GN + cc] =
                make_float2(acc[mi][ni][0] + bv.x, acc[mi][ni][1] + bv.y);
            *(float2*)&C[(size_t)(rr + 8) * GN + cc] =
                make_float2(acc[mi][ni][2] + bv.x, acc[mi][ni][3] + bv.y);
        }
    }
}

// ---------------- tensor-core flash attention (unchanged from R4) -----------
#define ATT_STAGE(kt) do {                                                   \
    int s_ = (kt) & 1; int k0_ = (kt) * 64;                                  \
    uint32_t st_ = SST + s_ * 32768;                                         \
    const size_t roff_ = base + (size_t)k0_ * HD_;                           \
    _Pragma("unroll")                                                        \
    for (int i_ = 0; i_ < 2; i_++) {                                         \
        int idx_ = tid + i_ * 256;                                           \
        int r_ = idx_ >> 3, u_ = idx_ & 7;                                   \
        uint32_t so_ = SW((uint32_t)(r_ * 128 + u_ * 16));                   \
        size_t go_ = roff_ + (size_t)r_ * HD_ + u_ * 8;                      \
        cp16(st_ + so_,          Kh_ + go_);                                 \
        cp16(st_ + 8192 + so_,   Kl_ + go_);                                 \
        cp16(st_ + 16384 + so_,  Vh_ + go_);                                 \
        cp16(st_ + 24576 + so_,  Vl_ + go_);                                 \
    }                                                                        \
    if (tid < 64)                                                            \
        smaskf[s_ * 64 + tid] = (1.0f - mask[b * S_ + k0_ + tid]) * -10000.0f; \
} while (0)

__global__ __launch_bounds__(256) void attn_tc(
    const __nv_bfloat16* __restrict__ Qh_, const __nv_bfloat16* __restrict__ Ql_,
    const __nv_bfloat16* __restrict__ Kh_, const __nv_bfloat16* __restrict__ Kl_,
    const __nv_bfloat16* __restrict__ Vh_, const __nv_bfloat16* __restrict__ Vl_,
    const float* __restrict__ mask,
    __nv_bfloat16* __restrict__ ctxh, __nv_bfloat16* __restrict__ ctxl)
{
    extern __shared__ char smraw[];
    const uint32_t sb = smem_u32(smraw);
    const uint32_t SQH = sb, SQL = sb + 16384;
    const uint32_t SST = sb + 32768;
    float* smaskf = (float*)(smraw + 98304);

    const int tid = threadIdx.x, lane = tid & 31, wid = tid >> 5;
    const int qt = gridDim.x - 1 - blockIdx.x;
    const int q0 = qt * 128;
    const int bh = blockIdx.y;
    const int b = bh >> 4, hh = bh & 15;
    const size_t base = (size_t)bh * (S_ * HD_);
    const int wq = wid * 16;

    {
        const size_t qoff = base + (size_t)q0 * HD_;
#pragma unroll
        for (int i = 0; i < 4; i++) {
            int idx = tid + i * 256;
            int r = idx >> 3, u = idx & 7;
            uint32_t so = SW((uint32_t)(r * 128 + u * 16));
            cp16(SQH + so, Qh_ + qoff + (size_t)r * HD_ + u * 8);
            cp16(SQL + so, Ql_ + qoff + (size_t)r * HD_ + u * 8);
        }
    }
    ATT_STAGE(0);
    CP_COMMIT();

    const uint32_t arow = (wq + (lane & 15)) * 128 + ((lane >> 4) << 4);
    const uint32_t bno  = ((lane & 7) + ((lane >> 4) << 3)) * 128
                        + (((lane >> 3) & 1) << 4);
    const uint32_t vro  = (((lane >> 3) & 1) * 8 + (lane & 7)) * 128
                        + ((lane >> 4) << 4);
    const int c0  = (lane & 3) * 2;
    const int rg0 = q0 + wq + (lane >> 2);
    const int rg1 = rg0 + 8;

    float o[8][4];
#pragma unroll
    for (int ni = 0; ni < 8; ni++)
#pragma unroll
        for (int r = 0; r < 4; r++) o[ni][r] = 0.0f;
    float m0r = -1e30f, m1r = -1e30f, l0r = 0.0f, l1r = 0.0f;

    const int ntile = 2 * qt + 2;
    for (int kt = 0; kt < ntile; kt++) {
        if (kt + 1 < ntile) ATT_STAGE(kt + 1);
        CP_COMMIT();
        CP_WAIT1();
        __syncthreads();

        const int k0 = kt * 64;
        if (k0 <= q0 + wq + 15) {
            const uint32_t sKh = SST + (kt & 1) * 32768;
            const uint32_t sKl = sKh + 8192;
            const uint32_t sVh = sKh + 16384;
            const uint32_t sVl = sKh + 24576;

            float s[8][4];
#pragma unroll
            for (int ni = 0; ni < 8; ni++)
#pragma unroll
                for (int r = 0; r < 4; r++) s[ni][r] = 0.0f;

#pragma unroll
            for (int k16 = 0; k16 < 4; k16++) {
                const uint32_t kb = k16 * 32;
                uint32_t aH[4], aL[4], kf[4][4];
                ldsm4(aH[0], aH[1], aH[2], aH[3], SQH + SW(arow + kb));
                ldsm4(aL[0], aL[1], aL[2], aL[3], SQL + SW(arow + kb));
#pragma unroll
                for (int nt = 0; nt < 4; nt++)
                    ldsm4(kf[nt][0], kf[nt][1], kf[nt][2], kf[nt][3],
                          sKh + SW(bno + nt * 2048 + kb));
#pragma unroll
                for (int ni = 0; ni < 8; ni++)
                    mma_bf16(s[ni], aH, kf[ni >> 1][(ni & 1) * 2],
                             kf[ni >> 1][(ni & 1) * 2 + 1]);
#pragma unroll
                for (int ni = 0; ni < 8; ni++)
                    mma_bf16(s[ni], aL, kf[ni >> 1][(ni & 1) * 2],
                             kf[ni >> 1][(ni & 1) * 2 + 1]);
#pragma unroll
                for (int nt = 0; nt < 4; nt++)
                    ldsm4(kf[nt][0], kf[nt][1], kf[nt][2], kf[nt][3],
                          sKl + SW(bno + nt * 2048 + kb));
#pragma unroll
                for (int ni = 0; ni < 8; ni++)
                    mma_bf16(s[ni], aH, kf[ni >> 1][(ni & 1) * 2],
                             kf[ni >> 1][(ni & 1) * 2 + 1]);
            }

            const float* mrow = smaskf + (kt & 1) * 64;
            const bool needc = (k0 + 63 > q0 + wq);
#pragma unroll
            for (int ni = 0; ni < 8; ni++) {
                const int kg = k0 + ni * 8 + c0;
                const float ma = mrow[ni * 8 + c0];
                const float mb = mrow[ni * 8 + c0 + 1];
                s[ni][0] = s[ni][0] * 0.125f + ma;
                s[ni][1] = s[ni][1] * 0.125f + mb;
                s[ni][2] = s[ni][2] * 0.125f + ma;
                s[ni][3] = s[ni][3] * 0.125f + mb;
                if (needc) {
                    if (kg > rg0)     s[ni][0] -= 1e10f;
                    if (kg + 1 > rg0) s[ni][1] -= 1e10f;
                    if (kg > rg1)     s[ni][2] -= 1e10f;
                    if (kg + 1 > rg1) s[ni][3] -= 1e10f;
                }
            }

            float mx0 = -1e30f, mx1 = -1e30f;
#pragma unroll
            for (int ni = 0; ni < 8; ni++) {
                mx0 = fmaxf(mx0, fmaxf(s[ni][0], s[ni][1]));
                mx1 = fmaxf(mx1, fmaxf(s[ni][2], s[ni][3]));
            }
            mx0 = fmaxf(mx0, __shfl_xor_sync(0xffffffffu, mx0, 1));
            mx0 = fmaxf(mx0, __shfl_xor_sync(0xffffffffu, mx0, 2));
            mx1 = fmaxf(mx1, __shfl_xor_sync(0xffffffffu, mx1, 1));
            mx1 = fmaxf(mx1, __shfl_xor_sync(0xffffffffu, mx1, 2));
            const float nm0 = fmaxf(m0r, mx0), nm1 = fmaxf(m1r, mx1);
            const float al0 = __expf(m0r - nm0), al1 = __expf(m1r - nm1);
            float ps0 = 0.0f, ps1 = 0.0f;
#pragma unroll
            for (int ni = 0; ni < 8; ni++) {
                s[ni][0] = __expf(s[ni][0] - nm0); ps0 += s[ni][0];
                s[ni][1] = __expf(s[ni][1] - nm0); ps0 += s[ni][1];
                s[ni][2] = __expf(s[ni][2] - nm1); ps1 += s[ni][2];
                s[ni][3] = __expf(s[ni][3] - nm1); ps1 += s[ni][3];
            }
            ps0 += __shfl_xor_sync(0xffffffffu, ps0, 1);
            ps0 += __shfl_xor_sync(0xffffffffu, ps0, 2);
            ps1 += __shfl_xor_sync(0xffffffffu, ps1, 1);
            ps1 += __shfl_xor_sync(0xffffffffu, ps1, 2);
            l0r = l0r * al0 + ps0;  m0r = nm0;
            l1r = l1r * al1 + ps1;  m1r = nm1;
#pragma unroll
            for (int ni = 0; ni < 8; ni++) {
                o[ni][0] *= al0; o[ni][1] *= al0;
                o[ni][2] *= al1; o[ni][3] *= al1;
            }

#pragma unroll
            for (int jb = 0; jb < 4; jb++) {
                uint32_t aPh[4], aPl[4];
#pragma unroll
                for (int t = 0; t < 2; t++) {
                    const int ti = jb * 2 + t;
                    uint32_t u0, u1, u2, u3;
                    float l0 = trunc_split(s[ti][0], u0);
                    float l1 = trunc_split(s[ti][1], u1);
                    float l2 = trunc_split(s[ti][2], u2);
                    float l3 = trunc_split(s[ti][3], u3);
                    aPh[t * 2 + 0] = __byte_perm(u0, u1, 0x7632);
                    aPh[t * 2 + 1] = __byte_perm(u2, u3, 0x7632);
                    aPl[t * 2 + 0] = pack_bf2(l0, l1);
                    aPl[t * 2 + 1] = pack_bf2(l2, l3);
                }
                uint32_t vf[4][4];
                const uint32_t vbase = vro + jb * 2048;
#pragma unroll
                for (int nt = 0; nt < 4; nt++)
                    ldsm4t(vf[nt], sVh + SW(vbase + nt * 32));
#pragma unroll
                for (int ni = 0; ni < 8; ni++)
                    mma_bf16(o[ni], aPh, vf[ni >> 1][(ni & 1) * 2],
                             vf[ni >> 1][(ni & 1) * 2 + 1]);
#pragma unroll
                for (int ni = 0; ni < 8; ni++)
                    mma_bf16(o[ni], aPl, vf[ni >> 1][(ni & 1) * 2],
                             vf[ni >> 1][(ni & 1) * 2 + 1]);
#pragma unroll
                for (int nt = 0; nt < 4; nt++)
                    ldsm4t(vf[nt], sVl + SW(vbase + nt * 32));
#pragma unroll
                for (int ni = 0; ni < 8; ni++)
                    mma_bf16(o[ni], aPh, vf[ni >> 1][(ni & 1) * 2],
                             vf[ni >> 1][(ni & 1) * 2 + 1]);
            }
        }
        __syncthreads();
    }

    const float i0 = 1.0f / l0r, i1 = 1.0f / l1r;
    const size_t row0 = ((size_t)b * S_ + rg0) * D_ + hh * HD_;
    const size_t row1 = ((size_t)b * S_ + rg1) * D_ + hh * HD_;
#pragma unroll
    for (int ni = 0; ni < 8; ni++) {
        const int d = ni * 8 + c0;
        float v0 = o[ni][0] * i0, v1 = o[ni][1] * i0;
        float v2 = o[ni][2] * i1, v3 = o[ni][3] * i1;
        uint32_t u0, u1, u2, u3;
        float l0 = trunc_split(v0, u0), l1 = trunc_split(v1, u1);
        float l2 = trunc_split(v2, u2), l3 = trunc_split(v3, u3);
        *(uint32_t*)(ctxh + row0 + d) = __byte_perm(u0, u1, 0x7632);
        *(uint32_t*)(ctxh + row1 + d) = __byte_perm(u2, u3, 0x7632);
        *(uint32_t*)(ctxl + row0 + d) = pack_bf2(l0, l1);
        *(uint32_t*)(ctxl + row1 + d) = pack_bf2(l2, l3);
    }
}

// ---------------------------------------------------------------------------
extern "C" void kernel_launch(void* const* d_in, const int* in_sizes, int n_in,
                              void* d_out, int out_size)
{
    const float* X    = (const float*)d_in[0];
    const float* mask = (const float*)d_in[1];
    const float* Wq   = (const float*)d_in[2];
    const float* bq   = (const float*)d_in[3];
    const float* Wk   = (const float*)d_in[4];
    const float* bk   = (const float*)d_in[5];
    const float* Wv   = (const float*)d_in[6];
    const float* bv   = (const float*)d_in[7];
    const float* Wo   = (const float*)d_in[8];
    const float* bo   = (const float*)d_in[9];
    float* out = (float*)d_out;

    int8_t *pA12, *pW12;
    float* pam;
    __nv_bfloat16 *pAh, *pAl, *pWh, *pWl, *pQh, *pQl, *pKh, *pKl, *pVh, *pVl;
    cudaGetSymbolAddress((void**)&pA12, g_A12);
    cudaGetSymbolAddress((void**)&pW12, g_W12);
    cudaGetSymbolAddress((void**)&pam, g_amax);
    cudaGetSymbolAddress((void**)&pAh, g_Ahi);
    cudaGetSymbolAddress((void**)&pAl, g_Alo);
    cudaGetSymbolAddress((void**)&pWh, g_Whi);
    cudaGetSymbolAddress((void**)&pWl, g_Wlo);
    cudaGetSymbolAddress((void**)&pQh, g_Qh);
    cudaGetSymbolAddress((void**)&pQl, g_Ql);
    cudaGetSymbolAddress((void**)&pKh, g_Kh);
    cudaGetSymbolAddress((void**)&pKl, g_Kl);
    cudaGetSymbolAddress((void**)&pVh, g_Vh);
    cudaGetSymbolAddress((void**)&pVl, g_Vl);

    const int GEMM_SMEM = 3 * 32768;
    cudaFuncSetAttribute(gemm_s8, cudaFuncAttributeMaxDynamicSharedMemorySize, GEMM_SMEM);
    cudaFuncSetAttribute(gemm_tc, cudaFuncAttributeMaxDynamicSharedMemorySize, GEMM_SMEM);
    const int ATTN_SMEM = 98304 + 512;
    cudaFuncSetAttribute(attn_tc, cudaFuncAttributeMaxDynamicSharedMemorySize, ATTN_SMEM);

    const size_t WS8 = (size_t)GN * 16 * 128;

    reset_amax<<<1, 32>>>();
    amax_k<<<512, 256>>>(X, pam + 0, M_ * GK / 4);
    amax_k<<<256, 256>>>(Wq, pam + 1, GK * GN / 4);
    amax_k<<<256, 256>>>(Wk, pam + 2, GK * GN / 4);
    amax_k<<<256, 256>>>(Wv, pam + 3, GK * GN / 4);

    quant_act<<<M_ * GK / 16 / 256, 256>>>(X, pA12, pam + 0);
    dim3 tb(32, 8), tg(GN / 32, GK / 32);
    tquant_w<<<tg, tb>>>(Wq, pW12 + 0 * WS8, pam + 1);
    tquant_w<<<tg, tb>>>(Wk, pW12 + 1 * WS8, pam + 2);
    tquant_w<<<tg, tb>>>(Wv, pW12 + 2 * WS8, pam + 3);
    transpose_split_w<<<tg, tb>>>(Wo, pWh, pWl);

    OutP op = {bq, bk, bv, pQh, pQl, pKh, pKl, pVh, pVl};
    gemm_s8<<<dim3(GN / 128, M_ / 128, 3), 256, GEMM_SMEM>>>(pA12, pW12, pam, op);

    dim3 ga(S_ / 128, B_ * H_);
    attn_tc<<<ga, 256, ATTN_SMEM>>>(pQh, pQl, pKh, pKl, pVh, pVl, mask, pAh, pAl);

    dim3 gg(GN / 128, M_ / 128);
    gemm_tc<<<gg, 256, GEMM_SMEM>>>(pAh, pAl, pWh, pWl, bo, out);
}

// round 7
// speedup vs baseline: 2.6285x; 2.6285x over previous
#include <cuda_runtime.h>
#include <cuda_fp16.h>
#include <cstdint>

#define B_   2
#define S_   2048
#define D_   1024
#define H_   16
#define HD_  64
#define M_   (B_ * S_)   // 4096
#define GN   D_
#define GK   D_

// ---------------- scratch (__device__ globals; no allocs allowed) ----------
__device__ __half g_Xh[M_ * GK], g_Xl[M_ * GK];      // X hi/lo (f16 split)
__device__ __half g_Wh[4][GK * GN];                  // W q/k/v/o, rn(f16), [N][K]
__device__ __half g_Qh[M_ * D_], g_Ql[M_ * D_];      // head layout [bh][s][d]
__device__ __half g_Kh[M_ * D_];
__device__ __half g_Vh[M_ * D_];
__device__ __half g_Ch[M_ * D_], g_Cl[M_ * D_];      // ctx hi/lo [B,S,D]

// ---------------- PTX helpers (sm_80+ only; tcgen05 rejected here) ---------
__device__ __forceinline__ uint32_t smem_u32(const void* p) {
    uint32_t a;
    asm("{ .reg .u64 t; cvta.to.shared.u64 t, %1; cvt.u32.u64 %0, t; }"
        : "=r"(a) : "l"(p));
    return a;
}
#define SW(o) ((o) ^ (((o) >> 3) & 0x70))
__device__ __forceinline__ void cp16(uint32_t d, const void* g) {
    asm volatile("cp.async.cg.shared.global [%0], [%1], 16;" :: "r"(d), "l"(g) : "memory");
}
#define CP_COMMIT() asm volatile("cp.async.commit_group;" ::: "memory")
#define CP_WAIT1()  asm volatile("cp.async.wait_group 1;" ::: "memory")

__device__ __forceinline__ void ldsm4(uint32_t& r0, uint32_t& r1,
                                      uint32_t& r2, uint32_t& r3, uint32_t a) {
    asm volatile("ldmatrix.sync.aligned.m8n8.x4.shared.b16 {%0,%1,%2,%3}, [%4];"
                 : "=r"(r0), "=r"(r1), "=r"(r2), "=r"(r3) : "r"(a));
}
__device__ __forceinline__ void ldsm4t(uint32_t* r, uint32_t a) {
    asm volatile("ldmatrix.sync.aligned.m8n8.x4.trans.shared.b16 {%0,%1,%2,%3}, [%4];"
                 : "=r"(r[0]), "=r"(r[1]), "=r"(r[2]), "=r"(r[3]) : "r"(a));
}
__device__ __forceinline__ void mma_f16(float* c, const uint32_t* a,
                                        uint32_t b0, uint32_t b1) {
    asm volatile(
        "mma.sync.aligned.m16n8k16.row.col.f32.f16.f16.f32 "
        "{%0,%1,%2,%3}, {%4,%5,%6,%7}, {%8,%9}, {%0,%1,%2,%3};"
        : "+f"(c[0]), "+f"(c[1]), "+f"(c[2]), "+f"(c[3])
        : "r"(a[0]), "r"(a[1]), "r"(a[2]), "r"(a[3]), "r"(b0), "r"(b1));
}
__device__ __forceinline__ uint32_t h2u(__half2 h) {
    return *reinterpret_cast<uint32_t*>(&h);
}
// split pair (v0,v1) -> packed f16 hi + packed f16 lo
__device__ __forceinline__ void split2(float v0, float v1,
                                       uint32_t& hi, uint32_t& lo) {
    __half2 h = __float22half2_rn(make_float2(v0, v1));
    float2 f = __half22float2(h);
    __half2 l = __float22half2_rn(make_float2(v0 - f.x, v1 - f.y));
    hi = h2u(h);
    lo = h2u(l);
}

// ---------------- conversion kernels ----------------------------------------
__global__ __launch_bounds__(256) void split_f16(
    const float* __restrict__ in, __half* __restrict__ hi,
    __half* __restrict__ lo)
{
    int i = blockIdx.x * 256 + threadIdx.x;
    float4 v = ((const float4*)in)[i];
    uint32_t h0, l0, h1, l1;
    split2(v.x, v.y, h0, l0);
    split2(v.z, v.w, h1, l1);
    ((uint32_t*)hi)[2 * i]     = h0;
    ((uint32_t*)hi)[2 * i + 1] = h1;
    ((uint32_t*)lo)[2 * i]     = l0;
    ((uint32_t*)lo)[2 * i + 1] = l1;
}

// W [K][N] f32 -> rn(f16) transposed [N][K]
__global__ __launch_bounds__(256) void transpose_w_f16(
    const float* __restrict__ W, __half* __restrict__ wh)
{
    __shared__ float t[32][33];
    const int n0 = blockIdx.x * 32, k0 = blockIdx.y * 32;
    const int tx = threadIdx.x, ty = threadIdx.y;   // (32, 8)
#pragma unroll
    for (int i = 0; i < 32; i += 8)
        t[ty + i][tx] = W[(size_t)(k0 + ty + i) * GN + n0 + tx];
    __syncthreads();
#pragma unroll
    for (int i = 0; i < 32; i += 8)
        wh[(size_t)(n0 + ty + i) * GK + k0 + tx] = __float2half_rn(t[tx][ty + i]);
}

// ---------------- f16 2-pass GEMM: C = (Ah+Al) @ rn(W)^T + bias -------------
// 128x128 CTA tile, 8 warps (32x64), 16 K-chunks of 64, 2-stage cp.async,
// both passes per chunk load (Ah|Al|Wh in one 48KB stage).
// mode 0: fp32 row-major C (bias biasC)
// mode 1: blockIdx.z = 0/1/2 -> Q (hi+lo) / K (hi) / V (hi) in head layout
struct QKVOut {
    const float *bq, *bk, *bv;
    __half *qh, *ql, *kh, *vh;
};

#define G2_LOAD(c) do {                                                      \
    uint32_t st_ = sb + ((c) & 1) * 49152;                                   \
    _Pragma("unroll")                                                        \
    for (int i_ = 0; i_ < 4; i_++) {                                         \
        int idx_ = tid + i_ * 256;                                           \
        int r_ = idx_ >> 3, u_ = idx_ & 7;                                   \
        uint32_t so_ = SW((uint32_t)(r_ * 128 + u_ * 16));                   \
        size_t ga_ = (size_t)(m0 + r_) * GK + (c) * 64 + u_ * 8;             \
        size_t gw_ = (size_t)(n0 + r_) * GK + (c) * 64 + u_ * 8;             \
        cp16(st_ + so_,         Ah + ga_);                                   \
        cp16(st_ + 16384 + so_, Al + ga_);                                   \
        cp16(st_ + 32768 + so_, Wh + gw_);                                   \
    }                                                                        \
} while (0)

__global__ __launch_bounds__(256) void gemm2p(
    const __half* __restrict__ Ah, const __half* __restrict__ Al,
    const __half* __restrict__ Whb, QKVOut op,
    const float* __restrict__ biasC, float* __restrict__ C, int mode)
{
    extern __shared__ char smc[];
    const uint32_t sb = smem_u32(smc);
    const int tid = threadIdx.x, lane = tid & 31, wid = tid >> 5;
    const int m0 = blockIdx.y * 128, n0 = blockIdx.x * 128;
    const int z = blockIdx.z;
    const __half* Wh = Whb + (mode ? (size_t)z * (GK * GN) : 0);
    const int wm = (wid & 3) * 32, wn = (wid >> 2) * 64;

    float acc[2][8][4];
#pragma unroll
    for (int mi = 0; mi < 2; mi++)
#pragma unroll
        for (int ni = 0; ni < 8; ni++)
#pragma unroll
            for (int r = 0; r < 4; r++) acc[mi][ni][r] = 0.0f;

    uint32_t aoff[2], boff[4];
#pragma unroll
    for (int mi = 0; mi < 2; mi++)
        aoff[mi] = (wm + mi * 16 + (lane & 15)) * 128 + ((lane >> 4) << 4);
#pragma unroll
    for (int nt = 0; nt < 4; nt++)
        boff[nt] = (wn + nt * 16 + (lane & 7) + ((lane >> 4) << 3)) * 128
                 + (((lane >> 3) & 1) << 4);

    G2_LOAD(0); CP_COMMIT();

    for (int c = 0; c < 16; c++) {
        if (c + 1 < 16) G2_LOAD(c + 1);
        CP_COMMIT();
        CP_WAIT1();
        __syncthreads();
        const uint32_t sAh = sb + (c & 1) * 49152;
        const uint32_t sAl = sAh + 16384;
        const uint32_t sW  = sAh + 32768;
#pragma unroll
        for (int k16 = 0; k16 < 4; k16++) {
            const uint32_t kb = k16 * 32;
            uint32_t aH[2][4], aL[2][4], w[4][4];
            ldsm4(aH[0][0], aH[0][1], aH[0][2], aH[0][3], sAh + SW(aoff[0] + kb));
            ldsm4(aH[1][0], aH[1][1], aH[1][2], aH[1][3], sAh + SW(aoff[1] + kb));
            ldsm4(aL[0][0], aL[0][1], aL[0][2], aL[0][3], sAl + SW(aoff[0] + kb));
            ldsm4(aL[1][0], aL[1][1], aL[1][2], aL[1][3], sAl + SW(aoff[1] + kb));
#pragma unroll
            for (int nt = 0; nt < 4; nt++)
                ldsm4(w[nt][0], w[nt][1], w[nt][2], w[nt][3],
                      sW + SW(boff[nt] + kb));
#pragma unroll
            for (int mi = 0; mi < 2; mi++)
#pragma unroll
                for (int ni = 0; ni < 8; ni++) {
                    mma_f16(acc[mi][ni], aH[mi],
                            w[ni >> 1][(ni & 1) * 2], w[ni >> 1][(ni & 1) * 2 + 1]);
                    mma_f16(acc[mi][ni], aL[mi],
                            w[ni >> 1][(ni & 1) * 2], w[ni >> 1][(ni & 1) * 2 + 1]);
                }
        }
        __syncthreads();
    }

    // epilogue
    const float* bias = mode ? ((z == 0) ? op.bq : (z == 1) ? op.bk : op.bv)
                             : biasC;
    const int r0 = lane >> 2, cq = (lane & 3) * 2;
#pragma unroll
    for (int mi = 0; mi < 2; mi++) {
#pragma unroll
        for (int ni = 0; ni < 8; ni++) {
            const int rr = m0 + wm + mi * 16 + r0;
            const int cc = n0 + wn + ni * 8 + cq;
            const float2 bv = *(const float2*)&bias[cc];
            float v0 = acc[mi][ni][0] + bv.x, v1 = acc[mi][ni][1] + bv.y;
            float v2 = acc[mi][ni][2] + bv.x, v3 = acc[mi][ni][3] + bv.y;
            if (mode == 0) {
                *(float2*)&C[(size_t)rr * GN + cc] = make_float2(v0, v1);
                *(float2*)&C[(size_t)(rr + 8) * GN + cc] = make_float2(v2, v3);
            } else {
                const int h = cc >> 6, d = cc & 63;
                const int bb = rr >> 11;
                const int s0 = rr & 2047, s1 = (rr + 8) & 2047;
                const size_t o0 = ((((size_t)bb * H_ + h) * S_ + s0) << 6) + d;
                const size_t o1 = ((((size_t)bb * H_ + h) * S_ + s1) << 6) + d;
                uint32_t h0, l0, h1, l1;
                split2(v0, v1, h0, l0);
                split2(v2, v3, h1, l1);
                if (z == 0) {
                    *(uint32_t*)(op.qh + o0) = h0;
                    *(uint32_t*)(op.qh + o1) = h1;
                    *(uint32_t*)(op.ql + o0) = l0;
                    *(uint32_t*)(op.ql + o1) = l1;
                } else if (z == 1) {
                    *(uint32_t*)(op.kh + o0) = h0;
                    *(uint32_t*)(op.kh + o1) = h1;
                } else {
                    *(uint32_t*)(op.vh + o0) = h0;
                    *(uint32_t*)(op.vh + o1) = h1;
                }
            }
        }
    }
}

// ---------------- f16 2-pass tensor-core flash attention --------------------
// CTA: 128 q x (b,h); 8 warps x 16 q-rows; k-tiles of 64, 2-stage (Kh|Vh 16KB).
// S = Qh.Kh + Ql.Kh;  O += Ph.Vh + Pl.Vh (P split in registers).
#define ATT_STAGE(kt) do {                                                   \
    int s_ = (kt) & 1; int k0_ = (kt) * 64;                                  \
    uint32_t st_ = SST + s_ * 16384;                                         \
    const size_t roff_ = base + (size_t)k0_ * HD_;                           \
    _Pragma("unroll")                                                        \
    for (int i_ = 0; i_ < 2; i_++) {                                         \
        int idx_ = tid + i_ * 256;                                           \
        int r_ = idx_ >> 3, u_ = idx_ & 7;                                   \
        uint32_t so_ = SW((uint32_t)(r_ * 128 + u_ * 16));                   \
        size_t go_ = roff_ + (size_t)r_ * HD_ + u_ * 8;                      \
        cp16(st_ + so_,        Kh_ + go_);                                   \
        cp16(st_ + 8192 + so_, Vh_ + go_);                                   \
    }                                                                        \
    if (tid < 64)                                                            \
        smaskf[s_ * 64 + tid] = (1.0f - mask[b * S_ + k0_ + tid]) * -10000.0f; \
} while (0)

__global__ __launch_bounds__(256) void attn_tc(
    const __half* __restrict__ Qh_, const __half* __restrict__ Ql_,
    const __half* __restrict__ Kh_, const __half* __restrict__ Vh_,
    const float* __restrict__ mask,
    __half* __restrict__ ctxh, __half* __restrict__ ctxl)
{
    extern __shared__ char smraw[];
    const uint32_t sb = smem_u32(smraw);
    const uint32_t SQH = sb, SQL = sb + 16384;
    const uint32_t SST = sb + 32768;            // 2 stages x 16KB
    float* smaskf = (float*)(smraw + 65536);

    const int tid = threadIdx.x, lane = tid & 31, wid = tid >> 5;
    const int qt = gridDim.x - 1 - blockIdx.x;  // heavy tiles first
    const int q0 = qt * 128;
    const int bh = blockIdx.y;
    const int b = bh >> 4, hh = bh & 15;
    const size_t base = (size_t)bh * (S_ * HD_);
    const int wq = wid * 16;

    {
        const size_t qoff = base + (size_t)q0 * HD_;
#pragma unroll
        for (int i = 0; i < 4; i++) {
            int idx = tid + i * 256;
            int r = idx >> 3, u = idx & 7;
            uint32_t so = SW((uint32_t)(r * 128 + u * 16));
            cp16(SQH + so, Qh_ + qoff + (size_t)r * HD_ + u * 8);
            cp16(SQL + so, Ql_ + qoff + (size_t)r * HD_ + u * 8);
        }
    }
    ATT_STAGE(0);
    CP_COMMIT();

    const uint32_t arow = (wq + (lane & 15)) * 128 + ((lane >> 4) << 4);
    const uint32_t bno  = ((lane & 7) + ((lane >> 4) << 3)) * 128
                        + (((lane >> 3) & 1) << 4);
    const uint32_t vro  = (((lane >> 3) & 1) * 8 + (lane & 7)) * 128
                        + ((lane >> 4) << 4);
    const int c0  = (lane & 3) * 2;
    const int rg0 = q0 + wq + (lane >> 2);
    const int rg1 = rg0 + 8;

    float o[8][4];
#pragma unroll
    for (int ni = 0; ni < 8; ni++)
#pragma unroll
        for (int r = 0; r < 4; r++) o[ni][r] = 0.0f;
    float m0r = -1e30f, m1r = -1e30f, l0r = 0.0f, l1r = 0.0f;

    const int ntile = 2 * qt + 2;
    for (int kt = 0; kt < ntile; kt++) {
        if (kt + 1 < ntile) ATT_STAGE(kt + 1);
        CP_COMMIT();
        CP_WAIT1();
        __syncthreads();

        const int k0 = kt * 64;
        if (k0 <= q0 + wq + 15) {
            const uint32_t sKh = SST + (kt & 1) * 16384;
            const uint32_t sVh = sKh + 8192;

            float s[8][4];
#pragma unroll
            for (int ni = 0; ni < 8; ni++)
#pragma unroll
                for (int r = 0; r < 4; r++) s[ni][r] = 0.0f;

            // ---- S = (Qh + Ql).Kh ----
#pragma unroll
            for (int k16 = 0; k16 < 4; k16++) {
                const uint32_t kb = k16 * 32;
                uint32_t aH[4], aL[4], kf[4][4];
                ldsm4(aH[0], aH[1], aH[2], aH[3], SQH + SW(arow + kb));
                ldsm4(aL[0], aL[1], aL[2], aL[3], SQL + SW(arow + kb));
#pragma unroll
                for (int nt = 0; nt < 4; nt++)
                    ldsm4(kf[nt][0], kf[nt][1], kf[nt][2], kf[nt][3],
                          sKh + SW(bno + nt * 2048 + kb));
#pragma unroll
                for (int ni = 0; ni < 8; ni++) {
                    mma_f16(s[ni], aH, kf[ni >> 1][(ni & 1) * 2],
                            kf[ni >> 1][(ni & 1) * 2 + 1]);
                    mma_f16(s[ni], aL, kf[ni >> 1][(ni & 1) * 2],
                            kf[ni >> 1][(ni & 1) * 2 + 1]);
                }
            }

            // ---- scale + pad + causal ----
            const float* mrow = smaskf + (kt & 1) * 64;
            const bool needc = (k0 + 63 > q0 + wq);
#pragma unroll
            for (int ni = 0; ni < 8; ni++) {
                const int kg = k0 + ni * 8 + c0;
                const float ma = mrow[ni * 8 + c0];
                const float mb = mrow[ni * 8 + c0 + 1];
                s[ni][0] = s[ni][0] * 0.125f + ma;
                s[ni][1] = s[ni][1] * 0.125f + mb;
                s[ni][2] = s[ni][2] * 0.125f + ma;
                s[ni][3] = s[ni][3] * 0.125f + mb;
                if (needc) {
                    if (kg > rg0)     s[ni][0] -= 1e10f;
                    if (kg + 1 > rg0) s[ni][1] -= 1e10f;
                    if (kg > rg1)     s[ni][2] -= 1e10f;
                    if (kg + 1 > rg1) s[ni][3] -= 1e10f;
                }
            }

            // ---- register online softmax ----
            float mx0 = -1e30f, mx1 = -1e30f;
#pragma unroll
            for (int ni = 0; ni < 8; ni++) {
                mx0 = fmaxf(mx0, fmaxf(s[ni][0], s[ni][1]));
                mx1 = fmaxf(mx1, fmaxf(s[ni][2], s[ni][3]));
            }
            mx0 = fmaxf(mx0, __shfl_xor_sync(0xffffffffu, mx0, 1));
            mx0 = fmaxf(mx0, __shfl_xor_sync(0xffffffffu, mx0, 2));
            mx1 = fmaxf(mx1, __shfl_xor_sync(0xffffffffu, mx1, 1));
            mx1 = fmaxf(mx1, __shfl_xor_sync(0xffffffffu, mx1, 2));
            const float nm0 = fmaxf(m0r, mx0), nm1 = fmaxf(m1r, mx1);
            const float al0 = __expf(m0r - nm0), al1 = __expf(m1r - nm1);
            float ps0 = 0.0f, ps1 = 0.0f;
#pragma unroll
            for (int ni = 0; ni < 8; ni++) {
                s[ni][0] = __expf(s[ni][0] - nm0); ps0 += s[ni][0];
                s[ni][1] = __expf(s[ni][1] - nm0); ps0 += s[ni][1];
                s[ni][2] = __expf(s[ni][2] - nm1); ps1 += s[ni][2];
                s[ni][3] = __expf(s[ni][3] - nm1); ps1 += s[ni][3];
            }
            ps0 += __shfl_xor_sync(0xffffffffu, ps0, 1);
            ps0 += __shfl_xor_sync(0xffffffffu, ps0, 2);
            ps1 += __shfl_xor_sync(0xffffffffu, ps1, 1);
            ps1 += __shfl_xor_sync(0xffffffffu, ps1, 2);
            l0r = l0r * al0 + ps0;  m0r = nm0;
            l1r = l1r * al1 + ps1;  m1r = nm1;
#pragma unroll
            for (int ni = 0; ni < 8; ni++) {
                o[ni][0] *= al0; o[ni][1] *= al0;
                o[ni][2] *= al1; o[ni][3] *= al1;
            }

            // ---- O += (Ph + Pl).Vh ----
#pragma unroll
            for (int jb = 0; jb < 4; jb++) {
                uint32_t aPh[4], aPl[4];
#pragma unroll
                for (int t = 0; t < 2; t++) {
                    const int ti = jb * 2 + t;
                    split2(s[ti][0], s[ti][1], aPh[t * 2 + 0], aPl[t * 2 + 0]);
                    split2(s[ti][2], s[ti][3], aPh[t * 2 + 1], aPl[t * 2 + 1]);
                }
                uint32_t vf[4][4];
                const uint32_t vbase = vro + jb * 2048;
#pragma unroll
                for (int nt = 0; nt < 4; nt++)
                    ldsm4t(vf[nt], sVh + SW(vbase + nt * 32));
#pragma unroll
                for (int ni = 0; ni < 8; ni++) {
                    mma_f16(o[ni], aPh, vf[ni >> 1][(ni & 1) * 2],
                            vf[ni >> 1][(ni & 1) * 2 + 1]);
                    mma_f16(o[ni], aPl, vf[ni >> 1][(ni & 1) * 2],
                            vf[ni >> 1][(ni & 1) * 2 + 1]);
                }
            }
        }
        __syncthreads();
    }

    // ---- normalize + write ctx hi/lo (f16) in [B,S,D] layout ----
    const float i0 = 1.0f / l0r, i1 = 1.0f / l1r;
    const size_t row0 = ((size_t)b * S_ + rg0) * D_ + hh * HD_;
    const size_t row1 = ((size_t)b * S_ + rg1) * D_ + hh * HD_;
#pragma unroll
    for (int ni = 0; ni < 8; ni++) {
        const int d = ni * 8 + c0;
        uint32_t h0, l0, h1, l1;
        split2(o[ni][0] * i0, o[ni][1] * i0, h0, l0);
        split2(o[ni][2] * i1, o[ni][3] * i1, h1, l1);
        *(uint32_t*)(ctxh + row0 + d) = h0;
        *(uint32_t*)(ctxh + row1 + d) = h1;
        *(uint32_t*)(ctxl + row0 + d) = l0;
        *(uint32_t*)(ctxl + row1 + d) = l1;
    }
}

// ---------------------------------------------------------------------------
extern "C" void kernel_launch(void* const* d_in, const int* in_sizes, int n_in,
                              void* d_out, int out_size)
{
    const float* X    = (const float*)d_in[0];
    const float* mask = (const float*)d_in[1];
    const float* Wq   = (const float*)d_in[2];
    const float* bq   = (const float*)d_in[3];
    const float* Wk   = (const float*)d_in[4];
    const float* bk   = (const float*)d_in[5];
    const float* Wv   = (const float*)d_in[6];
    const float* bv   = (const float*)d_in[7];
    const float* Wo   = (const float*)d_in[8];
    const float* bo   = (const float*)d_in[9];
    float* out = (float*)d_out;

    __half *pXh, *pXl, *pWh, *pQh, *pQl, *pKh, *pVh, *pCh, *pCl;
    cudaGetSymbolAddress((void**)&pXh, g_Xh);
    cudaGetSymbolAddress((void**)&pXl, g_Xl);
    cudaGetSymbolAddress((void**)&pWh, g_Wh);
    cudaGetSymbolAddress((void**)&pQh, g_Qh);
    cudaGetSymbolAddress((void**)&pQl, g_Ql);
    cudaGetSymbolAddress((void**)&pKh, g_Kh);
    cudaGetSymbolAddress((void**)&pVh, g_Vh);
    cudaGetSymbolAddress((void**)&pCh, g_Ch);
    cudaGetSymbolAddress((void**)&pCl, g_Cl);

    const int GEMM_SMEM = 2 * 49152;                 // 96 KB
    cudaFuncSetAttribute(gemm2p, cudaFuncAttributeMaxDynamicSharedMemorySize,
                         GEMM_SMEM);
    const int ATTN_SMEM = 65536 + 512;               // 64.5 KB
    cudaFuncSetAttribute(attn_tc, cudaFuncAttributeMaxDynamicSharedMemorySize,
                         ATTN_SMEM);

    const size_t WSZ = (size_t)GK * GN;

    split_f16<<<M_ * GK / 1024, 256>>>(X, pXh, pXl);
    dim3 tb(32, 8), tg(GN / 32, GK / 32);
    transpose_w_f16<<<tg, tb>>>(Wq, pWh + 0 * WSZ);
    transpose_w_f16<<<tg, tb>>>(Wk, pWh + 1 * WSZ);
    transpose_w_f16<<<tg, tb>>>(Wv, pWh + 2 * WSZ);
    transpose_w_f16<<<tg, tb>>>(Wo, pWh + 3 * WSZ);

    QKVOut op = {bq, bk, bv, pQh, pQl, pKh, pVh};
    gemm2p<<<dim3(GN / 128, M_ / 128, 3), 256, GEMM_SMEM>>>(
        pXh, pXl, pWh, op, nullptr, nullptr, 1);

    dim3 ga(S_ / 128, B_ * H_);
    attn_tc<<<ga, 256, ATTN_SMEM>>>(pQh, pQl, pKh, pVh, mask, pCh, pCl);

    gemm2p<<<dim3(GN / 128, M_ / 128, 1), 256, GEMM_SMEM>>>(
        pCh, pCl, pWh + 3 * WSZ, op, bo, out, 0);
}

// round 8
// speedup vs baseline: 2.8836x; 1.0971x over previous
#include <cuda_runtime.h>
#include <cuda_fp16.h>
#include <cstdint>

#define B_   2
#define S_   2048
#define D_   1024
#define H_   16
#define HD_  64
#define M_   (B_ * S_)   // 4096
#define GN   D_
#define GK   D_

// ---------------- scratch (__device__ globals; no allocs allowed) ----------
__device__ __half g_Xh[M_ * GK], g_Xl[M_ * GK];      // X hi/lo (f16 split)
__device__ __half g_Wh[4][GK * GN];                  // W q/k/v/o, rn(f16), [N][K]
__device__ __half g_Qh[M_ * D_], g_Ql[M_ * D_];      // head layout [bh][s][d]
__device__ __half g_Kh[M_ * D_];
__device__ __half g_Vh[M_ * D_];
__device__ __half g_Ch[M_ * D_];                     // ctx rn(f16) [B,S,D]

// ---------------- PTX helpers (sm_80+ only; tcgen05 rejected here) ---------
__device__ __forceinline__ uint32_t smem_u32(const void* p) {
    uint32_t a;
    asm("{ .reg .u64 t; cvta.to.shared.u64 t, %1; cvt.u32.u64 %0, t; }"
        : "=r"(a) : "l"(p));
    return a;
}
#define SW(o) ((o) ^ (((o) >> 3) & 0x70))
__device__ __forceinline__ void cp16(uint32_t d, const void* g) {
    asm volatile("cp.async.cg.shared.global [%0], [%1], 16;" :: "r"(d), "l"(g) : "memory");
}
#define CP_COMMIT() asm volatile("cp.async.commit_group;" ::: "memory")
#define CP_WAIT1()  asm volatile("cp.async.wait_group 1;" ::: "memory")

__device__ __forceinline__ void ldsm4(uint32_t& r0, uint32_t& r1,
                                      uint32_t& r2, uint32_t& r3, uint32_t a) {
    asm volatile("ldmatrix.sync.aligned.m8n8.x4.shared.b16 {%0,%1,%2,%3}, [%4];"
                 : "=r"(r0), "=r"(r1), "=r"(r2), "=r"(r3) : "r"(a));
}
__device__ __forceinline__ void ldsm4t(uint32_t* r, uint32_t a) {
    asm volatile("ldmatrix.sync.aligned.m8n8.x4.trans.shared.b16 {%0,%1,%2,%3}, [%4];"
                 : "=r"(r[0]), "=r"(r[1]), "=r"(r[2]), "=r"(r[3]) : "r"(a));
}
__device__ __forceinline__ void mma_f16(float* c, const uint32_t* a,
                                        uint32_t b0, uint32_t b1) {
    asm volatile(
        "mma.sync.aligned.m16n8k16.row.col.f32.f16.f16.f32 "
        "{%0,%1,%2,%3}, {%4,%5,%6,%7}, {%8,%9}, {%0,%1,%2,%3};"
        : "+f"(c[0]), "+f"(c[1]), "+f"(c[2]), "+f"(c[3])
        : "r"(a[0]), "r"(a[1]), "r"(a[2]), "r"(a[3]), "r"(b0), "r"(b1));
}
__device__ __forceinline__ uint32_t h2u(__half2 h) {
    return *reinterpret_cast<uint32_t*>(&h);
}
__device__ __forceinline__ uint32_t rn2(float v0, float v1) {
    return h2u(__float22half2_rn(make_float2(v0, v1)));
}
// split pair (v0,v1) -> packed f16 hi + packed f16 lo
__device__ __forceinline__ void split2(float v0, float v1,
                                       uint32_t& hi, uint32_t& lo) {
    __half2 h = __float22half2_rn(make_float2(v0, v1));
    float2 f = __half22float2(h);
    __half2 l = __float22half2_rn(make_float2(v0 - f.x, v1 - f.y));
    hi = h2u(h);
    lo = h2u(l);
}

// ---------------- conversion kernels ----------------------------------------
__global__ __launch_bounds__(256) void split_f16(
    const float* __restrict__ in, __half* __restrict__ hi,
    __half* __restrict__ lo)
{
    int i = blockIdx.x * 256 + threadIdx.x;
    float4 v = ((const float4*)in)[i];
    uint32_t h0, l0, h1, l1;
    split2(v.x, v.y, h0, l0);
    split2(v.z, v.w, h1, l1);
    ((uint32_t*)hi)[2 * i]     = h0;
    ((uint32_t*)hi)[2 * i + 1] = h1;
    ((uint32_t*)lo)[2 * i]     = l0;
    ((uint32_t*)lo)[2 * i + 1] = l1;
}

// All four W [K][N] f32 -> rn(f16) transposed [N][K]; blockIdx.z selects W
struct WPtrs { const float* w[4]; };
__global__ __launch_bounds__(256) void transpose_w_all(
    WPtrs ws, __half* __restrict__ whbase)
{
    __shared__ float t[32][33];
    const float* W = ws.w[blockIdx.z];
    __half* wh = whbase + (size_t)blockIdx.z * (GK * GN);
    const int n0 = blockIdx.x * 32, k0 = blockIdx.y * 32;
    const int tx = threadIdx.x, ty = threadIdx.y;   // (32, 8)
#pragma unroll
    for (int i = 0; i < 32; i += 8)
        t[ty + i][tx] = W[(size_t)(k0 + ty + i) * GN + n0 + tx];
    __syncthreads();
#pragma unroll
    for (int i = 0; i < 32; i += 8)
        wh[(size_t)(n0 + ty + i) * GK + k0 + tx] = __float2half_rn(t[tx][ty + i]);
}

// ---------------- f16 GEMM: C = (Ah [+ Al]) @ rn(W)^T + bias ----------------
// 128x128 CTA tile, 8 warps (32x64), 16 K-chunks of 64, 2-stage cp.async.
// 2-pass (hi+lo A) only where precision matters: Q projection (mode 1, z=0).
// K/V projections (z=1,2) and the Wo gemm (mode 0) are single-pass.
// mode 0: fp32 row-major C (bias biasC)
// mode 1: blockIdx.z = 0/1/2 -> Q (hi+lo) / K (hi) / V (hi) in head layout
struct QKVOut {
    const float *bq, *bk, *bv;
    __half *qh, *ql, *kh, *vh;
};

#define G2_LOAD(c) do {                                                      \
    uint32_t st_ = sb + ((c) & 1) * 49152;                                   \
    _Pragma("unroll")                                                        \
    for (int i_ = 0; i_ < 4; i_++) {                                         \
        int idx_ = tid + i_ * 256;                                           \
        int r_ = idx_ >> 3, u_ = idx_ & 7;                                   \
        uint32_t so_ = SW((uint32_t)(r_ * 128 + u_ * 16));                   \
        size_t ga_ = (size_t)(m0 + r_) * GK + (c) * 64 + u_ * 8;             \
        size_t gw_ = (size_t)(n0 + r_) * GK + (c) * 64 + u_ * 8;             \
        cp16(st_ + so_,         Ah + ga_);                                   \
        if (twop) cp16(st_ + 16384 + so_, Al + ga_);                         \
        cp16(st_ + 32768 + so_, Wh + gw_);                                   \
    }                                                                        \
} while (0)

__global__ __launch_bounds__(256) void gemm2p(
    const __half* __restrict__ Ah, const __half* __restrict__ Al,
    const __half* __restrict__ Whb, QKVOut op,
    const float* __restrict__ biasC, float* __restrict__ C, int mode)
{
    extern __shared__ char smc[];
    const uint32_t sb = smem_u32(smc);
    const int tid = threadIdx.x, lane = tid & 31, wid = tid >> 5;
    const int m0 = blockIdx.y * 128, n0 = blockIdx.x * 128;
    const int z = blockIdx.z;
    const bool twop = (mode == 1 && z == 0);
    const __half* Wh = Whb + (mode ? (size_t)z * (GK * GN) : 0);
    const int wm = (wid & 3) * 32, wn = (wid >> 2) * 64;

    float acc[2][8][4];
#pragma unroll
    for (int mi = 0; mi < 2; mi++)
#pragma unroll
        for (int ni = 0; ni < 8; ni++)
#pragma unroll
            for (int r = 0; r < 4; r++) acc[mi][ni][r] = 0.0f;

    uint32_t aoff[2], boff[4];
#pragma unroll
    for (int mi = 0; mi < 2; mi++)
        aoff[mi] = (wm + mi * 16 + (lane & 15)) * 128 + ((lane >> 4) << 4);
#pragma unroll
    for (int nt = 0; nt < 4; nt++)
        boff[nt] = (wn + nt * 16 + (lane & 7) + ((lane >> 4) << 3)) * 128
                 + (((lane >> 3) & 1) << 4);

    G2_LOAD(0); CP_COMMIT();

    for (int c = 0; c < 16; c++) {
        if (c + 1 < 16) G2_LOAD(c + 1);
        CP_COMMIT();
        CP_WAIT1();
        __syncthreads();
        const uint32_t sAh = sb + (c & 1) * 49152;
        const uint32_t sAl = sAh + 16384;
        const uint32_t sW  = sAh + 32768;
#pragma unroll
        for (int k16 = 0; k16 < 4; k16++) {
            const uint32_t kb = k16 * 32;
            uint32_t aH[2][4], aL[2][4], w[4][4];
            ldsm4(aH[0][0], aH[0][1], aH[0][2], aH[0][3], sAh + SW(aoff[0] + kb));
            ldsm4(aH[1][0], aH[1][1], aH[1][2], aH[1][3], sAh + SW(aoff[1] + kb));
            if (twop) {
                ldsm4(aL[0][0], aL[0][1], aL[0][2], aL[0][3], sAl + SW(aoff[0] + kb));
                ldsm4(aL[1][0], aL[1][1], aL[1][2], aL[1][3], sAl + SW(aoff[1] + kb));
            }
#pragma unroll
            for (int nt = 0; nt < 4; nt++)
                ldsm4(w[nt][0], w[nt][1], w[nt][2], w[nt][3],
                      sW + SW(boff[nt] + kb));
#pragma unroll
            for (int mi = 0; mi < 2; mi++)
#pragma unroll
                for (int ni = 0; ni < 8; ni++) {
                    mma_f16(acc[mi][ni], aH[mi],
                            w[ni >> 1][(ni & 1) * 2], w[ni >> 1][(ni & 1) * 2 + 1]);
                    if (twop)
                        mma_f16(acc[mi][ni], aL[mi],
                                w[ni >> 1][(ni & 1) * 2], w[ni >> 1][(ni & 1) * 2 + 1]);
                }
        }
        __syncthreads();
    }

    // epilogue
    const float* bias = mode ? ((z == 0) ? op.bq : (z == 1) ? op.bk : op.bv)
                             : biasC;
    const int r0 = lane >> 2, cq = (lane & 3) * 2;
#pragma unroll
    for (int mi = 0; mi < 2; mi++) {
#pragma unroll
        for (int ni = 0; ni < 8; ni++) {
            const int rr = m0 + wm + mi * 16 + r0;
            const int cc = n0 + wn + ni * 8 + cq;
            const float2 bv = *(const float2*)&bias[cc];
            float v0 = acc[mi][ni][0] + bv.x, v1 = acc[mi][ni][1] + bv.y;
            float v2 = acc[mi][ni][2] + bv.x, v3 = acc[mi][ni][3] + bv.y;
            if (mode == 0) {
                *(float2*)&C[(size_t)rr * GN + cc] = make_float2(v0, v1);
                *(float2*)&C[(size_t)(rr + 8) * GN + cc] = make_float2(v2, v3);
            } else {
                const int h = cc >> 6, d = cc & 63;
                const int bb = rr >> 11;
                const int s0 = rr & 2047, s1 = (rr + 8) & 2047;
                const size_t o0 = ((((size_t)bb * H_ + h) * S_ + s0) << 6) + d;
                const size_t o1 = ((((size_t)bb * H_ + h) * S_ + s1) << 6) + d;
                if (z == 0) {
                    uint32_t h0, l0, h1, l1;
                    split2(v0, v1, h0, l0);
                    split2(v2, v3, h1, l1);
                    *(uint32_t*)(op.qh + o0) = h0;
                    *(uint32_t*)(op.qh + o1) = h1;
                    *(uint32_t*)(op.ql + o0) = l0;
                    *(uint32_t*)(op.ql + o1) = l1;
                } else {
                    __half* oh = (z == 1) ? op.kh : op.vh;
                    *(uint32_t*)(oh + o0) = rn2(v0, v1);
                    *(uint32_t*)(oh + o1) = rn2(v2, v3);
                }
            }
        }
    }
}

// ---------------- f16 2-pass tensor-core flash attention --------------------
// CTA: 128 q x (b,h); 8 warps x 16 q-rows; k-tiles of 64, 2-stage (Kh|Vh 16KB).
// S = Qh.Kh + Ql.Kh;  O += Ph.Vh + Pl.Vh (P split in registers).
// Writes ctx as rn(f16) only (Wo gemm is single-pass).
#define ATT_STAGE(kt) do {                                                   \
    int s_ = (kt) & 1; int k0_ = (kt) * 64;                                  \
    uint32_t st_ = SST + s_ * 16384;                                         \
    const size_t roff_ = base + (size_t)k0_ * HD_;                           \
    _Pragma("unroll")                                                        \
    for (int i_ = 0; i_ < 2; i_++) {                                         \
        int idx_ = tid + i_ * 256;                                           \
        int r_ = idx_ >> 3, u_ = idx_ & 7;                                   \
        uint32_t so_ = SW((uint32_t)(r_ * 128 + u_ * 16));                   \
        size_t go_ = roff_ + (size_t)r_ * HD_ + u_ * 8;                      \
        cp16(st_ + so_,        Kh_ + go_);                                   \
        cp16(st_ + 8192 + so_, Vh_ + go_);                                   \
    }                                                                        \
    if (tid < 64)                                                            \
        smaskf[s_ * 64 + tid] = (1.0f - mask[b * S_ + k0_ + tid]) * -10000.0f; \
} while (0)

__global__ __launch_bounds__(256) void attn_tc(
    const __half* __restrict__ Qh_, const __half* __restrict__ Ql_,
    const __half* __restrict__ Kh_, const __half* __restrict__ Vh_,
    const float* __restrict__ mask, __half* __restrict__ ctxh)
{
    extern __shared__ char smraw[];
    const uint32_t sb = smem_u32(smraw);
    const uint32_t SQH = sb, SQL = sb + 16384;
    const uint32_t SST = sb + 32768;            // 2 stages x 16KB
    float* smaskf = (float*)(smraw + 65536);

    const int tid = threadIdx.x, lane = tid & 31, wid = tid >> 5;
    const int qt = gridDim.x - 1 - blockIdx.x;  // heavy tiles first
    const int q0 = qt * 128;
    const int bh = blockIdx.y;
    const int b = bh >> 4, hh = bh & 15;
    const size_t base = (size_t)bh * (S_ * HD_);
    const int wq = wid * 16;

    {
        const size_t qoff = base + (size_t)q0 * HD_;
#pragma unroll
        for (int i = 0; i < 4; i++) {
            int idx = tid + i * 256;
            int r = idx >> 3, u = idx & 7;
            uint32_t so = SW((uint32_t)(r * 128 + u * 16));
            cp16(SQH + so, Qh_ + qoff + (size_t)r * HD_ + u * 8);
            cp16(SQL + so, Ql_ + qoff + (size_t)r * HD_ + u * 8);
        }
    }
    ATT_STAGE(0);
    CP_COMMIT();

    const uint32_t arow = (wq + (lane & 15)) * 128 + ((lane >> 4) << 4);
    const uint32_t bno  = ((lane & 7) + ((lane >> 4) << 3)) * 128
                        + (((lane >> 3) & 1) << 4);
    const uint32_t vro  = (((lane >> 3) & 1) * 8 + (lane & 7)) * 128
                        + ((lane >> 4) << 4);
    const int c0  = (lane & 3) * 2;
    const int rg0 = q0 + wq + (lane >> 2);
    const int rg1 = rg0 + 8;

    float o[8][4];
#pragma unroll
    for (int ni = 0; ni < 8; ni++)
#pragma unroll
        for (int r = 0; r < 4; r++) o[ni][r] = 0.0f;
    float m0r = -1e30f, m1r = -1e30f, l0r = 0.0f, l1r = 0.0f;

    const int ntile = 2 * qt + 2;
    for (int kt = 0; kt < ntile; kt++) {
        if (kt + 1 < ntile) ATT_STAGE(kt + 1);
        CP_COMMIT();
        CP_WAIT1();
        __syncthreads();

        const int k0 = kt * 64;
        if (k0 <= q0 + wq + 15) {
            const uint32_t sKh = SST + (kt & 1) * 16384;
            const uint32_t sVh = sKh + 8192;

            float s[8][4];
#pragma unroll
            for (int ni = 0; ni < 8; ni++)
#pragma unroll
                for (int r = 0; r < 4; r++) s[ni][r] = 0.0f;

            // ---- S = (Qh + Ql).Kh ----
#pragma unroll
            for (int k16 = 0; k16 < 4; k16++) {
                const uint32_t kb = k16 * 32;
                uint32_t aH[4], aL[4], kf[4][4];
                ldsm4(aH[0], aH[1], aH[2], aH[3], SQH + SW(arow + kb));
                ldsm4(aL[0], aL[1], aL[2], aL[3], SQL + SW(arow + kb));
#pragma unroll
                for (int nt = 0; nt < 4; nt++)
                    ldsm4(kf[nt][0], kf[nt][1], kf[nt][2], kf[nt][3],
                          sKh + SW(bno + nt * 2048 + kb));
#pragma unroll
                for (int ni = 0; ni < 8; ni++) {
                    mma_f16(s[ni], aH, kf[ni >> 1][(ni & 1) * 2],
                            kf[ni >> 1][(ni & 1) * 2 + 1]);
                    mma_f16(s[ni], aL, kf[ni >> 1][(ni & 1) * 2],
                            kf[ni >> 1][(ni & 1) * 2 + 1]);
                }
            }

            // ---- scale + pad + causal ----
            const float* mrow = smaskf + (kt & 1) * 64;
            const bool needc = (k0 + 63 > q0 + wq);
#pragma unroll
            for (int ni = 0; ni < 8; ni++) {
                const int kg = k0 + ni * 8 + c0;
                const float ma = mrow[ni * 8 + c0];
                const float mb = mrow[ni * 8 + c0 + 1];
                s[ni][0] = s[ni][0] * 0.125f + ma;
                s[ni][1] = s[ni][1] * 0.125f + mb;
                s[ni][2] = s[ni][2] * 0.125f + ma;
                s[ni][3] = s[ni][3] * 0.125f + mb;
                if (needc) {
                    if (kg > rg0)     s[ni][0] -= 1e10f;
                    if (kg + 1 > rg0) s[ni][1] -= 1e10f;
                    if (kg > rg1)     s[ni][2] -= 1e10f;
                    if (kg + 1 > rg1) s[ni][3] -= 1e10f;
                }
            }

            // ---- register online softmax ----
            float mx0 = -1e30f, mx1 = -1e30f;
#pragma unroll
            for (int ni = 0; ni < 8; ni++) {
                mx0 = fmaxf(mx0, fmaxf(s[ni][0], s[ni][1]));
                mx1 = fmaxf(mx1, fmaxf(s[ni][2], s[ni][3]));
            }
            mx0 = fmaxf(mx0, __shfl_xor_sync(0xffffffffu, mx0, 1));
            mx0 = fmaxf(mx0, __shfl_xor_sync(0xffffffffu, mx0, 2));
            mx1 = fmaxf(mx1, __shfl_xor_sync(0xffffffffu, mx1, 1));
            mx1 = fmaxf(mx1, __shfl_xor_sync(0xffffffffu, mx1, 2));
            const float nm0 = fmaxf(m0r, mx0), nm1 = fmaxf(m1r, mx1);
            const float al0 = __expf(m0r - nm0), al1 = __expf(m1r - nm1);
            float ps0 = 0.0f, ps1 = 0.0f;
#pragma unroll
            for (int ni = 0; ni < 8; ni++) {
                s[ni][0] = __expf(s[ni][0] - nm0); ps0 += s[ni][0];
                s[ni][1] = __expf(s[ni][1] - nm0); ps0 += s[ni][1];
                s[ni][2] = __expf(s[ni][2] - nm1); ps1 += s[ni][2];
                s[ni][3] = __expf(s[ni][3] - nm1); ps1 += s[ni][3];
            }
            ps0 += __shfl_xor_sync(0xffffffffu, ps0, 1);
            ps0 += __shfl_xor_sync(0xffffffffu, ps0, 2);
            ps1 += __shfl_xor_sync(0xffffffffu, ps1, 1);
            ps1 += __shfl_xor_sync(0xffffffffu, ps1, 2);
            l0r = l0r * al0 + ps0;  m0r = nm0;
            l1r = l1r * al1 + ps1;  m1r = nm1;
#pragma unroll
            for (int ni = 0; ni < 8; ni++) {
                o[ni][0] *= al0; o[ni][1] *= al0;
                o[ni][2] *= al1; o[ni][3] *= al1;
            }

            // ---- O += (Ph + Pl).Vh ----
#pragma unroll
            for (int jb = 0; jb < 4; jb++) {
                uint32_t aPh[4], aPl[4];
#pragma unroll
                for (int t = 0; t < 2; t++) {
                    const int ti = jb * 2 + t;
                    split2(s[ti][0], s[ti][1], aPh[t * 2 + 0], aPl[t * 2 + 0]);
                    split2(s[ti][2], s[ti][3], aPh[t * 2 + 1], aPl[t * 2 + 1]);
                }
                uint32_t vf[4][4];
                const uint32_t vbase = vro + jb * 2048;
#pragma unroll
                for (int nt = 0; nt < 4; nt++)
                    ldsm4t(vf[nt], sVh + SW(vbase + nt * 32));
#pragma unroll
                for (int ni = 0; ni < 8; ni++) {
                    mma_f16(o[ni], aPh, vf[ni >> 1][(ni & 1) * 2],
                            vf[ni >> 1][(ni & 1) * 2 + 1]);
                    mma_f16(o[ni], aPl, vf[ni >> 1][(ni & 1) * 2],
                            vf[ni >> 1][(ni & 1) * 2 + 1]);
                }
            }
        }
        __syncthreads();
    }

    // ---- normalize + write ctx rn(f16) in [B,S,D] layout ----
    const float i0 = 1.0f / l0r, i1 = 1.0f / l1r;
    const size_t row0 = ((size_t)b * S_ + rg0) * D_ + hh * HD_;
    const size_t row1 = ((size_t)b * S_ + rg1) * D_ + hh * HD_;
#pragma unroll
    for (int ni = 0; ni < 8; ni++) {
        const int d = ni * 8 + c0;
        *(uint32_t*)(ctxh + row0 + d) = rn2(o[ni][0] * i0, o[ni][1] * i0);
        *(uint32_t*)(ctxh + row1 + d) = rn2(o[ni][2] * i1, o[ni][3] * i1);
    }
}

// ---------------------------------------------------------------------------
extern "C" void kernel_launch(void* const* d_in, const int* in_sizes, int n_in,
                              void* d_out, int out_size)
{
    const float* X    = (const float*)d_in[0];
    const float* mask = (const float*)d_in[1];
    const float* Wq   = (const float*)d_in[2];
    const float* bq   = (const float*)d_in[3];
    const float* Wk   = (const float*)d_in[4];
    const float* bk   = (const float*)d_in[5];
    const float* Wv   = (const float*)d_in[6];
    const float* bv   = (const float*)d_in[7];
    const float* Wo   = (const float*)d_in[8];
    const float* bo   = (const float*)d_in[9];
    float* out = (float*)d_out;

    __half *pXh, *pXl, *pWh, *pQh, *pQl, *pKh, *pVh, *pCh;
    cudaGetSymbolAddress((void**)&pXh, g_Xh);
    cudaGetSymbolAddress((void**)&pXl, g_Xl);
    cudaGetSymbolAddress((void**)&pWh, g_Wh);
    cudaGetSymbolAddress((void**)&pQh, g_Qh);
    cudaGetSymbolAddress((void**)&pQl, g_Ql);
    cudaGetSymbolAddress((void**)&pKh, g_Kh);
    cudaGetSymbolAddress((void**)&pVh, g_Vh);
    cudaGetSymbolAddress((void**)&pCh, g_Ch);

    const int GEMM_SMEM = 2 * 49152;                 // 96 KB
    cudaFuncSetAttribute(gemm2p, cudaFuncAttributeMaxDynamicSharedMemorySize,
                         GEMM_SMEM);
    const int ATTN_SMEM = 65536 + 512;               // 64.5 KB
    cudaFuncSetAttribute(attn_tc, cudaFuncAttributeMaxDynamicSharedMemorySize,
                         ATTN_SMEM);

    const size_t WSZ = (size_t)GK * GN;

    split_f16<<<M_ * GK / 1024, 256>>>(X, pXh, pXl);
    WPtrs ws = {{Wq, Wk, Wv, Wo}};
    transpose_w_all<<<dim3(GN / 32, GK / 32, 4), dim3(32, 8)>>>(ws, pWh);

    QKVOut op = {bq, bk, bv, pQh, pQl, pKh, pVh};
    gemm2p<<<dim3(GN / 128, M_ / 128, 3), 256, GEMM_SMEM>>>(
        pXh, pXl, pWh, op, nullptr, nullptr, 1);

    dim3 ga(S_ / 128, B_ * H_);
    attn_tc<<<ga, 256, ATTN_SMEM>>>(pQh, pQl, pKh, pVh, mask, pCh);

    gemm2p<<<dim3(GN / 128, M_ / 128, 1), 256, GEMM_SMEM>>>(
        pCh, pCh, pWh + 3 * WSZ, op, bo, out, 0);
}

// round 9
// speedup vs baseline: 4.5750x; 1.5865x over previous
#include <cuda_runtime.h>
#include <cuda_fp16.h>
#include <cstdint>

#define B_   2
#define S_   2048
#define D_   1024
#define H_   16
#define HD_  64
#define M_   (B_ * S_)   // 4096
#define GN   D_
#define GK   D_

#define LOG2E  1.4426950408889634f
#define SC2    (0.125f * LOG2E)            // score scale in base-2
#define NEGM2  (-10000.0f * LOG2E)         // pad-mask additive in base-2

// ---------------- scratch (__device__ globals; no allocs allowed) ----------
__device__ __half g_Xh[M_ * GK];                     // rn(f16) X [M][K]
__device__ __half g_Wh[4][GK * GN];                  // W q/k/v/o rn(f16) [N][K]
__device__ __half g_Qh[M_ * D_];                     // head layout [bh][s][d]
__device__ __half g_Kh[M_ * D_];
__device__ __half g_Vh[M_ * D_];
__device__ __half g_Ch[M_ * D_];                     // ctx rn(f16) [B,S,D]

// ---------------- PTX helpers (sm_80+ only; tcgen05 rejected here) ---------
__device__ __forceinline__ uint32_t smem_u32(const void* p) {
    uint32_t a;
    asm("{ .reg .u64 t; cvta.to.shared.u64 t, %1; cvt.u32.u64 %0, t; }"
        : "=r"(a) : "l"(p));
    return a;
}
#define SW(o) ((o) ^ (((o) >> 3) & 0x70))
__device__ __forceinline__ void cp16(uint32_t d, const void* g) {
    asm volatile("cp.async.cg.shared.global [%0], [%1], 16;" :: "r"(d), "l"(g) : "memory");
}
#define CP_COMMIT() asm volatile("cp.async.commit_group;" ::: "memory")
#define CP_WAIT1()  asm volatile("cp.async.wait_group 1;" ::: "memory")

__device__ __forceinline__ void ldsm4(uint32_t& r0, uint32_t& r1,
                                      uint32_t& r2, uint32_t& r3, uint32_t a) {
    asm volatile("ldmatrix.sync.aligned.m8n8.x4.shared.b16 {%0,%1,%2,%3}, [%4];"
                 : "=r"(r0), "=r"(r1), "=r"(r2), "=r"(r3) : "r"(a));
}
__device__ __forceinline__ void ldsm4t(uint32_t* r, uint32_t a) {
    asm volatile("ldmatrix.sync.aligned.m8n8.x4.trans.shared.b16 {%0,%1,%2,%3}, [%4];"
                 : "=r"(r[0]), "=r"(r[1]), "=r"(r[2]), "=r"(r[3]) : "r"(a));
}
__device__ __forceinline__ void mma_f16(float* c, const uint32_t* a,
                                        uint32_t b0, uint32_t b1) {
    asm volatile(
        "mma.sync.aligned.m16n8k16.row.col.f32.f16.f16.f32 "
        "{%0,%1,%2,%3}, {%4,%5,%6,%7}, {%8,%9}, {%0,%1,%2,%3};"
        : "+f"(c[0]), "+f"(c[1]), "+f"(c[2]), "+f"(c[3])
        : "r"(a[0]), "r"(a[1]), "r"(a[2]), "r"(a[3]), "r"(b0), "r"(b1));
}
__device__ __forceinline__ uint32_t h2u(__half2 h) {
    return *reinterpret_cast<uint32_t*>(&h);
}
__device__ __forceinline__ uint32_t rn2(float v0, float v1) {
    return h2u(__float22half2_rn(make_float2(v0, v1)));
}
__device__ __forceinline__ float ex2f(float x) {
    float y;
    asm("ex2.approx.ftz.f32 %0, %1;" : "=f"(y) : "f"(x));
    return y;
}

// ---------------- conversion kernels ----------------------------------------
__global__ __launch_bounds__(256) void rn_f16(
    const float* __restrict__ in, __half* __restrict__ out)
{
    int i = blockIdx.x * 256 + threadIdx.x;
    float4 v = ((const float4*)in)[i];
    ((uint32_t*)out)[2 * i]     = rn2(v.x, v.y);
    ((uint32_t*)out)[2 * i + 1] = rn2(v.z, v.w);
}

// All four W [K][N] f32 -> rn(f16) transposed [N][K]; blockIdx.z selects W
struct WPtrs { const float* w[4]; };
__global__ __launch_bounds__(256) void transpose_w_all(
    WPtrs ws, __half* __restrict__ whbase)
{
    __shared__ float t[32][33];
    const float* W = ws.w[blockIdx.z];
    __half* wh = whbase + (size_t)blockIdx.z * (GK * GN);
    const int n0 = blockIdx.x * 32, k0 = blockIdx.y * 32;
    const int tx = threadIdx.x, ty = threadIdx.y;   // (32, 8)
#pragma unroll
    for (int i = 0; i < 32; i += 8)
        t[ty + i][tx] = W[(size_t)(k0 + ty + i) * GN + n0 + tx];
    __syncthreads();
#pragma unroll
    for (int i = 0; i < 32; i += 8)
        wh[(size_t)(n0 + ty + i) * GK + k0 + tx] = __float2half_rn(t[tx][ty + i]);
}

// ---------------- f16 single-pass GEMM: C = rn(A) @ rn(W)^T + bias ----------
// 128x128 CTA tile, 8 warps (32x64), 16 K-chunks of 64, 2-stage cp.async.
// mode 0: fp32 row-major C (bias biasC)
// mode 1: blockIdx.z = 0/1/2 -> Q / K / V rn(f16) in head layout
struct QKVOut {
    const float *bq, *bk, *bv;
    __half *qh, *kh, *vh;
};

#define G_LOAD(c) do {                                                       \
    uint32_t st_ = sb + ((c) & 1) * 32768;                                   \
    _Pragma("unroll")                                                        \
    for (int i_ = 0; i_ < 4; i_++) {                                         \
        int idx_ = tid + i_ * 256;                                           \
        int r_ = idx_ >> 3, u_ = idx_ & 7;                                   \
        uint32_t so_ = SW((uint32_t)(r_ * 128 + u_ * 16));                   \
        cp16(st_ + so_,         Ah + (size_t)(m0 + r_) * GK + (c) * 64 + u_ * 8); \
        cp16(st_ + 16384 + so_, Wh + (size_t)(n0 + r_) * GK + (c) * 64 + u_ * 8); \
    }                                                                        \
} while (0)

__global__ __launch_bounds__(256) void gemm1p(
    const __half* __restrict__ Ah, const __half* __restrict__ Whb, QKVOut op,
    const float* __restrict__ biasC, float* __restrict__ C, int mode)
{
    extern __shared__ char smc[];
    const uint32_t sb = smem_u32(smc);
    const int tid = threadIdx.x, lane = tid & 31, wid = tid >> 5;
    const int m0 = blockIdx.y * 128, n0 = blockIdx.x * 128;
    const int z = blockIdx.z;
    const __half* Wh = Whb + (mode ? (size_t)z * (GK * GN) : 0);
    const int wm = (wid & 3) * 32, wn = (wid >> 2) * 64;

    float acc[2][8][4];
#pragma unroll
    for (int mi = 0; mi < 2; mi++)
#pragma unroll
        for (int ni = 0; ni < 8; ni++)
#pragma unroll
            for (int r = 0; r < 4; r++) acc[mi][ni][r] = 0.0f;

    uint32_t aoff[2], boff[4];
#pragma unroll
    for (int mi = 0; mi < 2; mi++)
        aoff[mi] = (wm + mi * 16 + (lane & 15)) * 128 + ((lane >> 4) << 4);
#pragma unroll
    for (int nt = 0; nt < 4; nt++)
        boff[nt] = (wn + nt * 16 + (lane & 7) + ((lane >> 4) << 3)) * 128
                 + (((lane >> 3) & 1) << 4);

    G_LOAD(0); CP_COMMIT();

    for (int c = 0; c < 16; c++) {
        if (c + 1 < 16) G_LOAD(c + 1);
        CP_COMMIT();
        CP_WAIT1();
        __syncthreads();
        const uint32_t sA = sb + (c & 1) * 32768;
        const uint32_t sW = sA + 16384;
#pragma unroll
        for (int k16 = 0; k16 < 4; k16++) {
            const uint32_t kb = k16 * 32;
            uint32_t a[2][4], w[4][4];
            ldsm4(a[0][0], a[0][1], a[0][2], a[0][3], sA + SW(aoff[0] + kb));
            ldsm4(a[1][0], a[1][1], a[1][2], a[1][3], sA + SW(aoff[1] + kb));
#pragma unroll
            for (int nt = 0; nt < 4; nt++)
                ldsm4(w[nt][0], w[nt][1], w[nt][2], w[nt][3],
                      sW + SW(boff[nt] + kb));
#pragma unroll
            for (int mi = 0; mi < 2; mi++)
#pragma unroll
                for (int ni = 0; ni < 8; ni++)
                    mma_f16(acc[mi][ni], a[mi],
                            w[ni >> 1][(ni & 1) * 2], w[ni >> 1][(ni & 1) * 2 + 1]);
        }
        __syncthreads();
    }

    // epilogue
    const float* bias = mode ? ((z == 0) ? op.bq : (z == 1) ? op.bk : op.bv)
                             : biasC;
    const int r0 = lane >> 2, cq = (lane & 3) * 2;
#pragma unroll
    for (int mi = 0; mi < 2; mi++) {
#pragma unroll
        for (int ni = 0; ni < 8; ni++) {
            const int rr = m0 + wm + mi * 16 + r0;
            const int cc = n0 + wn + ni * 8 + cq;
            const float2 bv = *(const float2*)&bias[cc];
            float v0 = acc[mi][ni][0] + bv.x, v1 = acc[mi][ni][1] + bv.y;
            float v2 = acc[mi][ni][2] + bv.x, v3 = acc[mi][ni][3] + bv.y;
            if (mode == 0) {
                *(float2*)&C[(size_t)rr * GN + cc] = make_float2(v0, v1);
                *(float2*)&C[(size_t)(rr + 8) * GN + cc] = make_float2(v2, v3);
            } else {
                const int h = cc >> 6, d = cc & 63;
                const int bb = rr >> 11;
                const int s0 = rr & 2047, s1 = (rr + 8) & 2047;
                const size_t o0 = ((((size_t)bb * H_ + h) * S_ + s0) << 6) + d;
                const size_t o1 = ((((size_t)bb * H_ + h) * S_ + s1) << 6) + d;
                __half* oh = (z == 0) ? op.qh : (z == 1) ? op.kh : op.vh;
                *(uint32_t*)(oh + o0) = rn2(v0, v1);
                *(uint32_t*)(oh + o1) = rn2(v2, v3);
            }
        }
    }
}

// ---------------- f16 single-pass flash attention (base-2 softmax) ----------
// CTA: 128 q x (b,h); 8 warps x 16 q-rows; k-tiles of 64, 2-stage (Kh|Vh 16KB).
// S = Q.K (single pass);  O += rn(P).V (single pass).
#define ATT_STAGE(kt) do {                                                   \
    int s_ = (kt) & 1; int k0_ = (kt) * 64;                                  \
    uint32_t st_ = SST + s_ * 16384;                                         \
    const size_t roff_ = base + (size_t)k0_ * HD_;                           \
    _Pragma("unroll")                                                        \
    for (int i_ = 0; i_ < 2; i_++) {                                         \
        int idx_ = tid + i_ * 256;                                           \
        int r_ = idx_ >> 3, u_ = idx_ & 7;                                   \
        uint32_t so_ = SW((uint32_t)(r_ * 128 + u_ * 16));                   \
        size_t go_ = roff_ + (size_t)r_ * HD_ + u_ * 8;                      \
        cp16(st_ + so_,        Kh_ + go_);                                   \
        cp16(st_ + 8192 + so_, Vh_ + go_);                                   \
    }                                                                        \
    if (tid < 64)                                                            \
        smaskf[s_ * 64 + tid] = (1.0f - mask[b * S_ + k0_ + tid]) * NEGM2;   \
} while (0)

__global__ __launch_bounds__(256) void attn_tc(
    const __half* __restrict__ Qh_, const __half* __restrict__ Kh_,
    const __half* __restrict__ Vh_, const float* __restrict__ mask,
    __half* __restrict__ ctxh)
{
    extern __shared__ char smraw[];
    const uint32_t sb = smem_u32(smraw);
    const uint32_t SQH = sb;                    // 16KB
    const uint32_t SST = sb + 16384;            // 2 stages x 16KB
    float* smaskf = (float*)(smraw + 49152);    // 2 x 64 floats

    const int tid = threadIdx.x, lane = tid & 31, wid = tid >> 5;
    const int qt = gridDim.x - 1 - blockIdx.x;  // heavy tiles first
    const int q0 = qt * 128;
    const int bh = blockIdx.y;
    const int b = bh >> 4, hh = bh & 15;
    const size_t base = (size_t)bh * (S_ * HD_);
    const int wq = wid * 16;

    {
        const size_t qoff = base + (size_t)q0 * HD_;
#pragma unroll
        for (int i = 0; i < 4; i++) {
            int idx = tid + i * 256;
            int r = idx >> 3, u = idx & 7;
            cp16(SQH + SW((uint32_t)(r * 128 + u * 16)),
                 Qh_ + qoff + (size_t)r * HD_ + u * 8);
        }
    }
    ATT_STAGE(0);
    CP_COMMIT();

    const uint32_t arow = (wq + (lane & 15)) * 128 + ((lane >> 4) << 4);
    const uint32_t bno  = ((lane & 7) + ((lane >> 4) << 3)) * 128
                        + (((lane >> 3) & 1) << 4);
    const uint32_t vro  = (((lane >> 3) & 1) * 8 + (lane & 7)) * 128
                        + ((lane >> 4) << 4);
    const int c0  = (lane & 3) * 2;
    const int rg0 = q0 + wq + (lane >> 2);
    const int rg1 = rg0 + 8;

    float o[8][4];
#pragma unroll
    for (int ni = 0; ni < 8; ni++)
#pragma unroll
        for (int r = 0; r < 4; r++) o[ni][r] = 0.0f;
    float m0r = -1e30f, m1r = -1e30f, l0r = 0.0f, l1r = 0.0f;

    const int ntile = 2 * qt + 2;
    for (int kt = 0; kt < ntile; kt++) {
        if (kt + 1 < ntile) ATT_STAGE(kt + 1);
        CP_COMMIT();
        CP_WAIT1();
        __syncthreads();

        const int k0 = kt * 64;
        if (k0 <= q0 + wq + 15) {       // warp-granular causal tile skip
            const uint32_t sKh = SST + (kt & 1) * 16384;
            const uint32_t sVh = sKh + 8192;

            float s[8][4];
#pragma unroll
            for (int ni = 0; ni < 8; ni++)
#pragma unroll
                for (int r = 0; r < 4; r++) s[ni][r] = 0.0f;

            // ---- S = Q.K (single pass) ----
#pragma unroll
            for (int k16 = 0; k16 < 4; k16++) {
                const uint32_t kb = k16 * 32;
                uint32_t aH[4], kf[4][4];
                ldsm4(aH[0], aH[1], aH[2], aH[3], SQH + SW(arow + kb));
#pragma unroll
                for (int nt = 0; nt < 4; nt++)
                    ldsm4(kf[nt][0], kf[nt][1], kf[nt][2], kf[nt][3],
                          sKh + SW(bno + nt * 2048 + kb));
#pragma unroll
                for (int ni = 0; ni < 8; ni++)
                    mma_f16(s[ni], aH, kf[ni >> 1][(ni & 1) * 2],
                            kf[ni >> 1][(ni & 1) * 2 + 1]);
            }

            // ---- scale (base-2) + pad + causal ----
            const float* mrow = smaskf + (kt & 1) * 64;
            const bool needc = (k0 + 63 > q0 + wq);
#pragma unroll
            for (int ni = 0; ni < 8; ni++) {
                const int kg = k0 + ni * 8 + c0;
                const float ma = mrow[ni * 8 + c0];
                const float mb = mrow[ni * 8 + c0 + 1];
                s[ni][0] = s[ni][0] * SC2 + ma;
                s[ni][1] = s[ni][1] * SC2 + mb;
                s[ni][2] = s[ni][2] * SC2 + ma;
                s[ni][3] = s[ni][3] * SC2 + mb;
                if (needc) {
                    if (kg > rg0)     s[ni][0] -= 1e10f;
                    if (kg + 1 > rg0) s[ni][1] -= 1e10f;
                    if (kg > rg1)     s[ni][2] -= 1e10f;
                    if (kg + 1 > rg1) s[ni][3] -= 1e10f;
                }
            }

            // ---- register online softmax (base-2) ----
            float mx0 = -1e30f, mx1 = -1e30f;
#pragma unroll
            for (int ni = 0; ni < 8; ni++) {
                mx0 = fmaxf(mx0, fmaxf(s[ni][0], s[ni][1]));
                mx1 = fmaxf(mx1, fmaxf(s[ni][2], s[ni][3]));
            }
            mx0 = fmaxf(mx0, __shfl_xor_sync(0xffffffffu, mx0, 1));
            mx0 = fmaxf(mx0, __shfl_xor_sync(0xffffffffu, mx0, 2));
            mx1 = fmaxf(mx1, __shfl_xor_sync(0xffffffffu, mx1, 1));
            mx1 = fmaxf(mx1, __shfl_xor_sync(0xffffffffu, mx1, 2));
            const float nm0 = fmaxf(m0r, mx0), nm1 = fmaxf(m1r, mx1);
            const float al0 = ex2f(m0r - nm0), al1 = ex2f(m1r - nm1);
            float ps0 = 0.0f, ps1 = 0.0f;
#pragma unroll
            for (int ni = 0; ni < 8; ni++) {
                s[ni][0] = ex2f(s[ni][0] - nm0); ps0 += s[ni][0];
                s[ni][1] = ex2f(s[ni][1] - nm0); ps0 += s[ni][1];
                s[ni][2] = ex2f(s[ni][2] - nm1); ps1 += s[ni][2];
                s[ni][3] = ex2f(s[ni][3] - nm1); ps1 += s[ni][3];
            }
            ps0 += __shfl_xor_sync(0xffffffffu, ps0, 1);
            ps0 += __shfl_xor_sync(0xffffffffu, ps0, 2);
            ps1 += __shfl_xor_sync(0xffffffffu, ps1, 1);
            ps1 += __shfl_xor_sync(0xffffffffu, ps1, 2);
            l0r = l0r * al0 + ps0;  m0r = nm0;
            l1r = l1r * al1 + ps1;  m1r = nm1;
#pragma unroll
            for (int ni = 0; ni < 8; ni++) {
                o[ni][0] *= al0; o[ni][1] *= al0;
                o[ni][2] *= al1; o[ni][3] *= al1;
            }

            // ---- O += rn(P).V (single pass) ----
#pragma unroll
            for (int jb = 0; jb < 4; jb++) {
                uint32_t aP[4];
#pragma unroll
                for (int t = 0; t < 2; t++) {
                    const int ti = jb * 2 + t;
                    aP[t * 2 + 0] = rn2(s[ti][0], s[ti][1]);
                    aP[t * 2 + 1] = rn2(s[ti][2], s[ti][3]);
                }
                uint32_t vf[4][4];
                const uint32_t vbase = vro + jb * 2048;
#pragma unroll
                for (int nt = 0; nt < 4; nt++)
                    ldsm4t(vf[nt], sVh + SW(vbase + nt * 32));
#pragma unroll
                for (int ni = 0; ni < 8; ni++)
                    mma_f16(o[ni], aP, vf[ni >> 1][(ni & 1) * 2],
                            vf[ni >> 1][(ni & 1) * 2 + 1]);
            }
        }
        __syncthreads();
    }

    // ---- normalize + write ctx rn(f16) in [B,S,D] layout ----
    const float i0 = 1.0f / l0r, i1 = 1.0f / l1r;
    const size_t row0 = ((size_t)b * S_ + rg0) * D_ + hh * HD_;
    const size_t row1 = ((size_t)b * S_ + rg1) * D_ + hh * HD_;
#pragma unroll
    for (int ni = 0; ni < 8; ni++) {
        const int d = ni * 8 + c0;
        *(uint32_t*)(ctxh + row0 + d) = rn2(o[ni][0] * i0, o[ni][1] * i0);
        *(uint32_t*)(ctxh + row1 + d) = rn2(o[ni][2] * i1, o[ni][3] * i1);
    }
}

// ---------------------------------------------------------------------------
extern "C" void kernel_launch(void* const* d_in, const int* in_sizes, int n_in,
                              void* d_out, int out_size)
{
    const float* X    = (const float*)d_in[0];
    const float* mask = (const float*)d_in[1];
    const float* Wq   = (const float*)d_in[2];
    const float* bq   = (const float*)d_in[3];
    const float* Wk   = (const float*)d_in[4];
    const float* bk   = (const float*)d_in[5];
    const float* Wv   = (const float*)d_in[6];
    const float* bv   = (const float*)d_in[7];
    const float* Wo   = (const float*)d_in[8];
    const float* bo   = (const float*)d_in[9];
    float* out = (float*)d_out;

    __half *pXh, *pWh, *pQh, *pKh, *pVh, *pCh;
    cudaGetSymbolAddress((void**)&pXh, g_Xh);
    cudaGetSymbolAddress((void**)&pWh, g_Wh);
    cudaGetSymbolAddress((void**)&pQh, g_Qh);
    cudaGetSymbolAddress((void**)&pKh, g_Kh);
    cudaGetSymbolAddress((void**)&pVh, g_Vh);
    cudaGetSymbolAddress((void**)&pCh, g_Ch);

    const int GEMM_SMEM = 2 * 32768;                 // 64 KB
    cudaFuncSetAttribute(gemm1p, cudaFuncAttributeMaxDynamicSharedMemorySize,
                         GEMM_SMEM);
    const int ATTN_SMEM = 49152 + 512;               // 48.5 KB
    cudaFuncSetAttribute(attn_tc, cudaFuncAttributeMaxDynamicSharedMemorySize,
                         ATTN_SMEM);

    const size_t WSZ = (size_t)GK * GN;

    rn_f16<<<M_ * GK / 1024, 256>>>(X, pXh);
    WPtrs ws = {{Wq, Wk, Wv, Wo}};
    transpose_w_all<<<dim3(GN / 32, GK / 32, 4), dim3(32, 8)>>>(ws, pWh);

    QKVOut op = {bq, bk, bv, pQh, pKh, pVh};
    gemm1p<<<dim3(GN / 128, M_ / 128, 3), 256, GEMM_SMEM>>>(
        pXh, pWh, op, nullptr, nullptr, 1);

    dim3 ga(S_ / 128, B_ * H_);
    attn_tc<<<ga, 256, ATTN_SMEM>>>(pQh, pKh, pVh, mask, pCh);

    gemm1p<<<dim3(GN / 128, M_ / 128, 1), 256, GEMM_SMEM>>>(
        pCh, pWh + 3 * WSZ, op, bo, out, 0);
}

// round 10
// speedup vs baseline: 4.8045x; 1.0502x over previous
#include <cuda_runtime.h>
#include <cuda_fp16.h>
#include <cstdint>

#define B_   2
#define S_   2048
#define D_   1024
#define H_   16
#define HD_  64
#define M_   (B_ * S_)   // 4096
#define GN   D_
#define GK   D_

#define LOG2E  1.4426950408889634f
#define SC2    (0.125f * LOG2E)            // folded into Q projection
#define NEGM2  (-10000.0f * LOG2E)         // pad-mask additive (base-2)
#define MSHIFT 4.0f                        // fixed softmax shift (see theory)
#define ONES2  0x3C003C00u                 // packed f16 {1, 1}

// ---------------- scratch (__device__ globals; no allocs allowed) ----------
__device__ __half g_Xh[M_ * GK];                     // rn(f16) X [M][K]
__device__ __half g_Wh[4][GK * GN];                  // W q/k/v/o rn(f16) [N][K]
__device__ __half g_Qh[M_ * D_];                     // head layout, pre-scaled
__device__ __half g_Kh[M_ * D_];
__device__ __half g_Vh[M_ * D_];
__device__ __half g_Ch[M_ * D_];                     // ctx rn(f16) [B,S,D]

// ---------------- PTX helpers (sm_80+ only; tcgen05 rejected here) ---------
__device__ __forceinline__ uint32_t smem_u32(const void* p) {
    uint32_t a;
    asm("{ .reg .u64 t; cvta.to.shared.u64 t, %1; cvt.u32.u64 %0, t; }"
        : "=r"(a) : "l"(p));
    return a;
}
#define SW(o) ((o) ^ (((o) >> 3) & 0x70))
__device__ __forceinline__ void cp16(uint32_t d, const void* g) {
    asm volatile("cp.async.cg.shared.global [%0], [%1], 16;" :: "r"(d), "l"(g) : "memory");
}
#define CP_COMMIT() asm volatile("cp.async.commit_group;" ::: "memory")
#define CP_WAIT1()  asm volatile("cp.async.wait_group 1;" ::: "memory")

__device__ __forceinline__ void ldsm4(uint32_t& r0, uint32_t& r1,
                                      uint32_t& r2, uint32_t& r3, uint32_t a) {
    asm volatile("ldmatrix.sync.aligned.m8n8.x4.shared.b16 {%0,%1,%2,%3}, [%4];"
                 : "=r"(r0), "=r"(r1), "=r"(r2), "=r"(r3) : "r"(a));
}
__device__ __forceinline__ void ldsm4t(uint32_t* r, uint32_t a) {
    asm volatile("ldmatrix.sync.aligned.m8n8.x4.trans.shared.b16 {%0,%1,%2,%3}, [%4];"
                 : "=r"(r[0]), "=r"(r[1]), "=r"(r[2]), "=r"(r[3]) : "r"(a));
}
__device__ __forceinline__ void mma_f16(float* c, const uint32_t* a,
                                        uint32_t b0, uint32_t b1) {
    asm volatile(
        "mma.sync.aligned.m16n8k16.row.col.f32.f16.f16.f32 "
        "{%0,%1,%2,%3}, {%4,%5,%6,%7}, {%8,%9}, {%0,%1,%2,%3};"
        : "+f"(c[0]), "+f"(c[1]), "+f"(c[2]), "+f"(c[3])
        : "r"(a[0]), "r"(a[1]), "r"(a[2]), "r"(a[3]), "r"(b0), "r"(b1));
}
__device__ __forceinline__ uint32_t h2u(__half2 h) {
    return *reinterpret_cast<uint32_t*>(&h);
}
__device__ __forceinline__ uint32_t rn2(float v0, float v1) {
    return h2u(__float22half2_rn(make_float2(v0, v1)));
}
__device__ __forceinline__ float ex2f(float x) {
    float y;
    asm("ex2.approx.ftz.f32 %0, %1;" : "=f"(y) : "f"(x));
    return y;
}

// ---------------- conversion kernels ----------------------------------------
__global__ __launch_bounds__(256) void rn_f16(
    const float* __restrict__ in, __half* __restrict__ out)
{
    int i = blockIdx.x * 256 + threadIdx.x;
    float4 v = ((const float4*)in)[i];
    ((uint32_t*)out)[2 * i]     = rn2(v.x, v.y);
    ((uint32_t*)out)[2 * i + 1] = rn2(v.z, v.w);
}

// All four W [K][N] f32 -> rn(f16) transposed [N][K]; blockIdx.z selects W
struct WPtrs { const float* w[4]; };
__global__ __launch_bounds__(256) void transpose_w_all(
    WPtrs ws, __half* __restrict__ whbase)
{
    __shared__ float t[32][33];
    const float* W = ws.w[blockIdx.z];
    __half* wh = whbase + (size_t)blockIdx.z * (GK * GN);
    const int n0 = blockIdx.x * 32, k0 = blockIdx.y * 32;
    const int tx = threadIdx.x, ty = threadIdx.y;   // (32, 8)
#pragma unroll
    for (int i = 0; i < 32; i += 8)
        t[ty + i][tx] = W[(size_t)(k0 + ty + i) * GN + n0 + tx];
    __syncthreads();
#pragma unroll
    for (int i = 0; i < 32; i += 8)
        wh[(size_t)(n0 + ty + i) * GK + k0 + tx] = __float2half_rn(t[tx][ty + i]);
}

// ---------------- f16 single-pass GEMM: C = rn(A) @ rn(W)^T + bias ----------
// 128x128 CTA tile, 8 warps (32x64), 16 K-chunks of 64, 2-stage cp.async.
// mode 0: fp32 row-major C (bias biasC)
// mode 1: blockIdx.z = 0/1/2 -> Q / K / V rn(f16) in head layout
//         (Q is pre-scaled by SC2 so attention scores are in base-2 units)
struct QKVOut {
    const float *bq, *bk, *bv;
    __half *qh, *kh, *vh;
};

#define G_LOAD(c) do {                                                       \
    uint32_t st_ = sb + ((c) & 1) * 32768;                                   \
    _Pragma("unroll")                                                        \
    for (int i_ = 0; i_ < 4; i_++) {                                         \
        int idx_ = tid + i_ * 256;                                           \
        int r_ = idx_ >> 3, u_ = idx_ & 7;                                   \
        uint32_t so_ = SW((uint32_t)(r_ * 128 + u_ * 16));                   \
        cp16(st_ + so_,         Ah + (size_t)(m0 + r_) * GK + (c) * 64 + u_ * 8); \
        cp16(st_ + 16384 + so_, Wh + (size_t)(n0 + r_) * GK + (c) * 64 + u_ * 8); \
    }                                                                        \
} while (0)

__global__ __launch_bounds__(256) void gemm1p(
    const __half* __restrict__ Ah, const __half* __restrict__ Whb, QKVOut op,
    const float* __restrict__ biasC, float* __restrict__ C, int mode)
{
    extern __shared__ char smc[];
    const uint32_t sb = smem_u32(smc);
    const int tid = threadIdx.x, lane = tid & 31, wid = tid >> 5;
    const int m0 = blockIdx.y * 128, n0 = blockIdx.x * 128;
    const int z = blockIdx.z;
    const __half* Wh = Whb + (mode ? (size_t)z * (GK * GN) : 0);
    const int wm = (wid & 3) * 32, wn = (wid >> 2) * 64;

    float acc[2][8][4];
#pragma unroll
    for (int mi = 0; mi < 2; mi++)
#pragma unroll
        for (int ni = 0; ni < 8; ni++)
#pragma unroll
            for (int r = 0; r < 4; r++) acc[mi][ni][r] = 0.0f;

    uint32_t aoff[2], boff[4];
#pragma unroll
    for (int mi = 0; mi < 2; mi++)
        aoff[mi] = (wm + mi * 16 + (lane & 15)) * 128 + ((lane >> 4) << 4);
#pragma unroll
    for (int nt = 0; nt < 4; nt++)
        boff[nt] = (wn + nt * 16 + (lane & 7) + ((lane >> 4) << 3)) * 128
                 + (((lane >> 3) & 1) << 4);

    G_LOAD(0); CP_COMMIT();

    for (int c = 0; c < 16; c++) {
        if (c + 1 < 16) G_LOAD(c + 1);
        CP_COMMIT();
        CP_WAIT1();
        __syncthreads();
        const uint32_t sA = sb + (c & 1) * 32768;
        const uint32_t sW = sA + 16384;
#pragma unroll
        for (int k16 = 0; k16 < 4; k16++) {
            const uint32_t kb = k16 * 32;
            uint32_t a[2][4], w[4][4];
            ldsm4(a[0][0], a[0][1], a[0][2], a[0][3], sA + SW(aoff[0] + kb));
            ldsm4(a[1][0], a[1][1], a[1][2], a[1][3], sA + SW(aoff[1] + kb));
#pragma unroll
            for (int nt = 0; nt < 4; nt++)
                ldsm4(w[nt][0], w[nt][1], w[nt][2], w[nt][3],
                      sW + SW(boff[nt] + kb));
#pragma unroll
            for (int mi = 0; mi < 2; mi++)
#pragma unroll
                for (int ni = 0; ni < 8; ni++)
                    mma_f16(acc[mi][ni], a[mi],
                            w[ni >> 1][(ni & 1) * 2], w[ni >> 1][(ni & 1) * 2 + 1]);
        }
        __syncthreads();
    }

    // epilogue
    const float* bias = mode ? ((z == 0) ? op.bq : (z == 1) ? op.bk : op.bv)
                             : biasC;
    const float osc = (mode == 1 && z == 0) ? SC2 : 1.0f;  // fold score scale into Q
    const int r0 = lane >> 2, cq = (lane & 3) * 2;
#pragma unroll
    for (int mi = 0; mi < 2; mi++) {
#pragma unroll
        for (int ni = 0; ni < 8; ni++) {
            const int rr = m0 + wm + mi * 16 + r0;
            const int cc = n0 + wn + ni * 8 + cq;
            const float2 bv = *(const float2*)&bias[cc];
            float v0 = (acc[mi][ni][0] + bv.x) * osc;
            float v1 = (acc[mi][ni][1] + bv.y) * osc;
            float v2 = (acc[mi][ni][2] + bv.x) * osc;
            float v3 = (acc[mi][ni][3] + bv.y) * osc;
            if (mode == 0) {
                *(float2*)&C[(size_t)rr * GN + cc] = make_float2(v0, v1);
                *(float2*)&C[(size_t)(rr + 8) * GN + cc] = make_float2(v2, v3);
            } else {
                const int h = cc >> 6, d = cc & 63;
                const int bb = rr >> 11;
                const int s0 = rr & 2047, s1 = (rr + 8) & 2047;
                const size_t o0 = ((((size_t)bb * H_ + h) * S_ + s0) << 6) + d;
                const size_t o1 = ((((size_t)bb * H_ + h) * S_ + s1) << 6) + d;
                __half* oh = (z == 0) ? op.qh : (z == 1) ? op.kh : op.vh;
                *(uint32_t*)(oh + o0) = rn2(v0, v1);
                *(uint32_t*)(oh + o1) = rn2(v2, v3);
            }
        }
    }
}

// ---------------- f16 flash attention, fixed-shift softmax ------------------
// CTA: 128 q x (b,h); 8 warps x 16 q-rows; k-tiles of 64, 2-stage (Kh|Vh 16KB).
// Q pre-scaled by SC2; mask additive pre-shifted by -MSHIFT.
// P = 2^(s + mask - M) directly (no running max / rescale / shfl);
// l accumulated via an all-ones B-fragment mma alongside P.V.
#define ATT_STAGE(kt) do {                                                   \
    int s_ = (kt) & 1; int k0_ = (kt) * 64;                                  \
    uint32_t st_ = SST + s_ * 16384;                                         \
    const size_t roff_ = base + (size_t)k0_ * HD_;                           \
    _Pragma("unroll")                                                        \
    for (int i_ = 0; i_ < 2; i_++) {                                         \
        int idx_ = tid + i_ * 256;                                           \
        int r_ = idx_ >> 3, u_ = idx_ & 7;                                   \
        uint32_t so_ = SW((uint32_t)(r_ * 128 + u_ * 16));                   \
        size_t go_ = roff_ + (size_t)r_ * HD_ + u_ * 8;                      \
        cp16(st_ + so_,        Kh_ + go_);                                   \
        cp16(st_ + 8192 + so_, Vh_ + go_);                                   \
    }                                                                        \
    if (tid < 64)                                                            \
        smaskf[s_ * 64 + tid] =                                              \
            (1.0f - mask[b * S_ + k0_ + tid]) * NEGM2 - MSHIFT;              \
} while (0)

__global__ __launch_bounds__(256) void attn_tc(
    const __half* __restrict__ Qh_, const __half* __restrict__ Kh_,
    const __half* __restrict__ Vh_, const float* __restrict__ mask,
    __half* __restrict__ ctxh)
{
    extern __shared__ char smraw[];
    const uint32_t sb = smem_u32(smraw);
    const uint32_t SQH = sb;                    // 16KB
    const uint32_t SST = sb + 16384;            // 2 stages x 16KB
    float* smaskf = (float*)(smraw + 49152);    // 2 x 64 floats

    const int tid = threadIdx.x, lane = tid & 31, wid = tid >> 5;
    const int qt = gridDim.x - 1 - blockIdx.x;  // heavy tiles first
    const int q0 = qt * 128;
    const int bh = blockIdx.y;
    const int b = bh >> 4, hh = bh & 15;
    const size_t base = (size_t)bh * (S_ * HD_);
    const int wq = wid * 16;

    {
        const size_t qoff = base + (size_t)q0 * HD_;
#pragma unroll
        for (int i = 0; i < 4; i++) {
            int idx = tid + i * 256;
            int r = idx >> 3, u = idx & 7;
            cp16(SQH + SW((uint32_t)(r * 128 + u * 16)),
                 Qh_ + qoff + (size_t)r * HD_ + u * 8);
        }
    }
    ATT_STAGE(0);
    CP_COMMIT();

    const uint32_t arow = (wq + (lane & 15)) * 128 + ((lane >> 4) << 4);
    const uint32_t bno  = ((lane & 7) + ((lane >> 4) << 3)) * 128
                        + (((lane >> 3) & 1) << 4);
    const uint32_t vro  = (((lane >> 3) & 1) * 8 + (lane & 7)) * 128
                        + ((lane >> 4) << 4);
    const int c0  = (lane & 3) * 2;
    const int rg0 = q0 + wq + (lane >> 2);
    const int rg1 = rg0 + 8;

    float o[8][4];
#pragma unroll
    for (int ni = 0; ni < 8; ni++)
#pragma unroll
        for (int r = 0; r < 4; r++) o[ni][r] = 0.0f;
    float lacc[4] = {0.0f, 0.0f, 0.0f, 0.0f};   // row sums via ones-mma

    const int ntile = 2 * qt + 2;
    for (int kt = 0; kt < ntile; kt++) {
        if (kt + 1 < ntile) ATT_STAGE(kt + 1);
        CP_COMMIT();
        CP_WAIT1();
        __syncthreads();

        const int k0 = kt * 64;
        if (k0 <= q0 + wq + 15) {       // warp-granular causal tile skip
            const uint32_t sKh = SST + (kt & 1) * 16384;
            const uint32_t sVh = sKh + 8192;

            float s[8][4];
#pragma unroll
            for (int ni = 0; ni < 8; ni++)
#pragma unroll
                for (int r = 0; r < 4; r++) s[ni][r] = 0.0f;

            // ---- S = Q.K (Q pre-scaled; scores in base-2 units) ----
#pragma unroll
            for (int k16 = 0; k16 < 4; k16++) {
                const uint32_t kb = k16 * 32;
                uint32_t aH[4], kf[4][4];
                ldsm4(aH[0], aH[1], aH[2], aH[3], SQH + SW(arow + kb));
#pragma unroll
                for (int nt = 0; nt < 4; nt++)
                    ldsm4(kf[nt][0], kf[nt][1], kf[nt][2], kf[nt][3],
                          sKh + SW(bno + nt * 2048 + kb));
#pragma unroll
                for (int ni = 0; ni < 8; ni++)
                    mma_f16(s[ni], aH, kf[ni >> 1][(ni & 1) * 2],
                            kf[ni >> 1][(ni & 1) * 2 + 1]);
            }

            // ---- mask(+M shift) add + causal ----
            const float* mrow = smaskf + (kt & 1) * 64;
            const bool needc = (k0 + 63 > q0 + wq);
#pragma unroll
            for (int ni = 0; ni < 8; ni++) {
                const int kg = k0 + ni * 8 + c0;
                const float ma = mrow[ni * 8 + c0];
                const float mb = mrow[ni * 8 + c0 + 1];
                s[ni][0] += ma;
                s[ni][1] += mb;
                s[ni][2] += ma;
                s[ni][3] += mb;
                if (needc) {
                    if (kg > rg0)     s[ni][0] -= 1e10f;
                    if (kg + 1 > rg0) s[ni][1] -= 1e10f;
                    if (kg > rg1)     s[ni][2] -= 1e10f;
                    if (kg + 1 > rg1) s[ni][3] -= 1e10f;
                }
            }

            // ---- P = 2^s; O += rn(P).V; l += rn(P).ones (no reductions) ----
#pragma unroll
            for (int jb = 0; jb < 4; jb++) {
                uint32_t aP[4];
#pragma unroll
                for (int t = 0; t < 2; t++) {
                    const int ti = jb * 2 + t;
                    aP[t * 2 + 0] = rn2(ex2f(s[ti][0]), ex2f(s[ti][1]));
                    aP[t * 2 + 1] = rn2(ex2f(s[ti][2]), ex2f(s[ti][3]));
                }
                uint32_t vf[4][4];
                const uint32_t vbase = vro + jb * 2048;
#pragma unroll
                for (int nt = 0; nt < 4; nt++)
                    ldsm4t(vf[nt], sVh + SW(vbase + nt * 32));
#pragma unroll
                for (int ni = 0; ni < 8; ni++)
                    mma_f16(o[ni], aP, vf[ni >> 1][(ni & 1) * 2],
                            vf[ni >> 1][(ni & 1) * 2 + 1]);
                mma_f16(lacc, aP, ONES2, ONES2);
            }
        }
        __syncthreads();
    }

    // ---- normalize + write ctx rn(f16) in [B,S,D] layout ----
    // lacc[0] = row rg0 sum, lacc[2] = row rg1 sum (all lanes identical).
    const float i0 = 1.0f / lacc[0], i1 = 1.0f / lacc[2];
    const size_t row0 = ((size_t)b * S_ + rg0) * D_ + hh * HD_;
    const size_t row1 = ((size_t)b * S_ + rg1) * D_ + hh * HD_;
#pragma unroll
    for (int ni = 0; ni < 8; ni++) {
        const int d = ni * 8 + c0;
        *(uint32_t*)(ctxh + row0 + d) = rn2(o[ni][0] * i0, o[ni][1] * i0);
        *(uint32_t*)(ctxh + row1 + d) = rn2(o[ni][2] * i1, o[ni][3] * i1);
    }
}

// ---------------------------------------------------------------------------
extern "C" void kernel_launch(void* const* d_in, const int* in_sizes, int n_in,
                              void* d_out, int out_size)
{
    const float* X    = (const float*)d_in[0];
    const float* mask = (const float*)d_in[1];
    const float* Wq   = (const float*)d_in[2];
    const float* bq   = (const float*)d_in[3];
    const float* Wk   = (const float*)d_in[4];
    const float* bk   = (const float*)d_in[5];
    const float* Wv   = (const float*)d_in[6];
    const float* bv   = (const float*)d_in[7];
    const float* Wo   = (const float*)d_in[8];
    const float* bo   = (const float*)d_in[9];
    float* out = (float*)d_out;

    __half *pXh, *pWh, *pQh, *pKh, *pVh, *pCh;
    cudaGetSymbolAddress((void**)&pXh, g_Xh);
    cudaGetSymbolAddress((void**)&pWh, g_Wh);
    cudaGetSymbolAddress((void**)&pQh, g_Qh);
    cudaGetSymbolAddress((void**)&pKh, g_Kh);
    cudaGetSymbolAddress((void**)&pVh, g_Vh);
    cudaGetSymbolAddress((void**)&pCh, g_Ch);

    const int GEMM_SMEM = 2 * 32768;                 // 64 KB
    cudaFuncSetAttribute(gemm1p, cudaFuncAttributeMaxDynamicSharedMemorySize,
                         GEMM_SMEM);
    const int ATTN_SMEM = 49152 + 512;               // 48.5 KB
    cudaFuncSetAttribute(attn_tc, cudaFuncAttributeMaxDynamicSharedMemorySize,
                         ATTN_SMEM);

    const size_t WSZ = (size_t)GK * GN;

    rn_f16<<<M_ * GK / 1024, 256>>>(X, pXh);
    WPtrs ws = {{Wq, Wk, Wv, Wo}};
    transpose_w_all<<<dim3(GN / 32, GK / 32, 4), dim3(32, 8)>>>(ws, pWh);

    QKVOut op = {bq, bk, bv, pQh, pKh, pVh};
    gemm1p<<<dim3(GN / 128, M_ / 128, 3), 256, GEMM_SMEM>>>(
        pXh, pWh, op, nullptr, nullptr, 1);

    dim3 ga(S_ / 128, B_ * H_);
    attn_tc<<<ga, 256, ATTN_SMEM>>>(pQh, pKh, pVh, mask, pCh);

    gemm1p<<<dim3(GN / 128, M_ / 128, 1), 256, GEMM_SMEM>>>(
        pCh, pWh + 3 * WSZ, op, bo, out, 0);
}

// round 11
// speedup vs baseline: 4.8443x; 1.0083x over previous
#include <cuda_runtime.h>
#include <cuda_fp16.h>
#include <cstdint>

#define B_   2
#define S_   2048
#define D_   1024
#define H_   16
#define HD_  64
#define M_   (B_ * S_)   // 4096
#define GN   D_
#define GK   D_

#define LOG2E  1.4426950408889634f
#define SC2    (0.125f * LOG2E)            // folded into Q projection
#define NEGM2  (-10000.0f * LOG2E)         // pad-mask additive (base-2)
#define MSHIFT 4.0f                        // fixed softmax shift
#define ONES2  0x3C003C00u                 // packed f16 {1, 1}

// ---------------- scratch (__device__ globals; no allocs allowed) ----------
__device__ __half g_Xh[M_ * GK];                     // rn(f16) X [M][K]
__device__ __half g_Wh[4][GK * GN];                  // W q/k/v/o rn(f16) [N][K]
__device__ __half g_Qh[M_ * D_];                     // head layout, pre-scaled
__device__ __half g_Kh[M_ * D_];
__device__ __half g_Vh[M_ * D_];
__device__ __half g_Ch[M_ * D_];                     // ctx rn(f16) [B,S,D]

// ---------------- PTX helpers (sm_80+ only; tcgen05 rejected here) ---------
__device__ __forceinline__ uint32_t smem_u32(const void* p) {
    uint32_t a;
    asm("{ .reg .u64 t; cvta.to.shared.u64 t, %1; cvt.u32.u64 %0, t; }"
        : "=r"(a) : "l"(p));
    return a;
}
#define SW(o) ((o) ^ (((o) >> 3) & 0x70))
__device__ __forceinline__ void cp16(uint32_t d, const void* g) {
    asm volatile("cp.async.cg.shared.global [%0], [%1], 16;" :: "r"(d), "l"(g) : "memory");
}
#define CP_COMMIT() asm volatile("cp.async.commit_group;" ::: "memory")
#define CP_WAIT1()  asm volatile("cp.async.wait_group 1;" ::: "memory")

__device__ __forceinline__ void ldsm4(uint32_t& r0, uint32_t& r1,
                                      uint32_t& r2, uint32_t& r3, uint32_t a) {
    asm volatile("ldmatrix.sync.aligned.m8n8.x4.shared.b16 {%0,%1,%2,%3}, [%4];"
                 : "=r"(r0), "=r"(r1), "=r"(r2), "=r"(r3) : "r"(a));
}
__device__ __forceinline__ void ldsm4t(uint32_t* r, uint32_t a) {
    asm volatile("ldmatrix.sync.aligned.m8n8.x4.trans.shared.b16 {%0,%1,%2,%3}, [%4];"
                 : "=r"(r[0]), "=r"(r[1]), "=r"(r[2]), "=r"(r[3]) : "r"(a));
}
__device__ __forceinline__ void mma_f16(float* c, const uint32_t* a,
                                        uint32_t b0, uint32_t b1) {
    asm volatile(
        "mma.sync.aligned.m16n8k16.row.col.f32.f16.f16.f32 "
        "{%0,%1,%2,%3}, {%4,%5,%6,%7}, {%8,%9}, {%0,%1,%2,%3};"
        : "+f"(c[0]), "+f"(c[1]), "+f"(c[2]), "+f"(c[3])
        : "r"(a[0]), "r"(a[1]), "r"(a[2]), "r"(a[3]), "r"(b0), "r"(b1));
}
__device__ __forceinline__ uint32_t h2u(__half2 h) {
    return *reinterpret_cast<uint32_t*>(&h);
}
__device__ __forceinline__ uint32_t rn2(float v0, float v1) {
    return h2u(__float22half2_rn(make_float2(v0, v1)));
}
__device__ __forceinline__ float ex2f(float x) {
    float y;
    asm("ex2.approx.ftz.f32 %0, %1;" : "=f"(y) : "f"(x));
    return y;
}

// ---------------- conversion kernels ----------------------------------------
__global__ __launch_bounds__(256) void rn_f16(
    const float* __restrict__ in, __half* __restrict__ out)
{
    int i = blockIdx.x * 256 + threadIdx.x;
    float4 v = ((const float4*)in)[i];
    ((uint32_t*)out)[2 * i]     = rn2(v.x, v.y);
    ((uint32_t*)out)[2 * i + 1] = rn2(v.z, v.w);
}

// All four W [K][N] f32 -> rn(f16) transposed [N][K]; blockIdx.z selects W
struct WPtrs { const float* w[4]; };
__global__ __launch_bounds__(256) void transpose_w_all(
    WPtrs ws, __half* __restrict__ whbase)
{
    __shared__ float t[32][33];
    const float* W = ws.w[blockIdx.z];
    __half* wh = whbase + (size_t)blockIdx.z * (GK * GN);
    const int n0 = blockIdx.x * 32, k0 = blockIdx.y * 32;
    const int tx = threadIdx.x, ty = threadIdx.y;   // (32, 8)
#pragma unroll
    for (int i = 0; i < 32; i += 8)
        t[ty + i][tx] = W[(size_t)(k0 + ty + i) * GN + n0 + tx];
    __syncthreads();
#pragma unroll
    for (int i = 0; i < 32; i += 8)
        wh[(size_t)(n0 + ty + i) * GK + k0 + tx] = __float2half_rn(t[tx][ty + i]);
}

// ---------------- f16 single-pass GEMM, 3-stage safe pipeline ---------------
// 128x128 CTA tile, 8 warps (32x64), 16 K-chunks of 64.
// Loop order: wait -> barrier -> prefetch(c+2) -> compute(c)  (race-free,
// single barrier per chunk).
// mode 0: fp32 row-major C (bias biasC)
// mode 1: blockIdx.z = 0/1/2 -> Q / K / V rn(f16) head layout (Q pre-scaled)
struct QKVOut {
    const float *bq, *bk, *bv;
    __half *qh, *kh, *vh;
};

#define G_LOAD(c) do {                                                       \
    uint32_t st_ = sb + ((c) % 3) * 32768;                                   \
    _Pragma("unroll")                                                        \
    for (int i_ = 0; i_ < 4; i_++) {                                         \
        int idx_ = tid + i_ * 256;                                           \
        int r_ = idx_ >> 3, u_ = idx_ & 7;                                   \
        uint32_t so_ = SW((uint32_t)(r_ * 128 + u_ * 16));                   \
        cp16(st_ + so_,         Ah + (size_t)(m0 + r_) * GK + (c) * 64 + u_ * 8); \
        cp16(st_ + 16384 + so_, Wh + (size_t)(n0 + r_) * GK + (c) * 64 + u_ * 8); \
    }                                                                        \
} while (0)

__global__ __launch_bounds__(256) void gemm1p(
    const __half* __restrict__ Ah, const __half* __restrict__ Whb, QKVOut op,
    const float* __restrict__ biasC, float* __restrict__ C, int mode)
{
    extern __shared__ char smc[];
    const uint32_t sb = smem_u32(smc);
    const int tid = threadIdx.x, lane = tid & 31, wid = tid >> 5;
    const int m0 = blockIdx.y * 128, n0 = blockIdx.x * 128;
    const int z = blockIdx.z;
    const __half* Wh = Whb + (mode ? (size_t)z * (GK * GN) : 0);
    const int wm = (wid & 3) * 32, wn = (wid >> 2) * 64;

    float acc[2][8][4];
#pragma unroll
    for (int mi = 0; mi < 2; mi++)
#pragma unroll
        for (int ni = 0; ni < 8; ni++)
#pragma unroll
            for (int r = 0; r < 4; r++) acc[mi][ni][r] = 0.0f;

    uint32_t aoff[2], boff[4];
#pragma unroll
    for (int mi = 0; mi < 2; mi++)
        aoff[mi] = (wm + mi * 16 + (lane & 15)) * 128 + ((lane >> 4) << 4);
#pragma unroll
    for (int nt = 0; nt < 4; nt++)
        boff[nt] = (wn + nt * 16 + (lane & 7) + ((lane >> 4) << 3)) * 128
                 + (((lane >> 3) & 1) << 4);

    G_LOAD(0); CP_COMMIT();
    G_LOAD(1); CP_COMMIT();

    for (int c = 0; c < 16; c++) {
        CP_WAIT1();                   // chunk c resident (c+1 may be in flight)
        __syncthreads();              // all readers of buffer (c+2)%3 are done
        if (c + 2 < 16) G_LOAD(c + 2);
        CP_COMMIT();

        const uint32_t sA = sb + (c % 3) * 32768;
        const uint32_t sW = sA + 16384;
#pragma unroll
        for (int k16 = 0; k16 < 4; k16++) {
            const uint32_t kb = k16 * 32;
            uint32_t a[2][4], w[4][4];
            ldsm4(a[0][0], a[0][1], a[0][2], a[0][3], sA + SW(aoff[0] + kb));
            ldsm4(a[1][0], a[1][1], a[1][2], a[1][3], sA + SW(aoff[1] + kb));
#pragma unroll
            for (int nt = 0; nt < 4; nt++)
                ldsm4(w[nt][0], w[nt][1], w[nt][2], w[nt][3],
                      sW + SW(boff[nt] + kb));
#pragma unroll
            for (int mi = 0; mi < 2; mi++)
#pragma unroll
                for (int ni = 0; ni < 8; ni++)
                    mma_f16(acc[mi][ni], a[mi],
                            w[ni >> 1][(ni & 1) * 2], w[ni >> 1][(ni & 1) * 2 + 1]);
        }
    }

    // epilogue
    const float* bias = mode ? ((z == 0) ? op.bq : (z == 1) ? op.bk : op.bv)
                             : biasC;
    const float osc = (mode == 1 && z == 0) ? SC2 : 1.0f;  // fold score scale
    const int r0 = lane >> 2, cq = (lane & 3) * 2;
#pragma unroll
    for (int mi = 0; mi < 2; mi++) {
#pragma unroll
        for (int ni = 0; ni < 8; ni++) {
            const int rr = m0 + wm + mi * 16 + r0;
            const int cc = n0 + wn + ni * 8 + cq;
            const float2 bv = *(const float2*)&bias[cc];
            float v0 = (acc[mi][ni][0] + bv.x) * osc;
            float v1 = (acc[mi][ni][1] + bv.y) * osc;
            float v2 = (acc[mi][ni][2] + bv.x) * osc;
            float v3 = (acc[mi][ni][3] + bv.y) * osc;
            if (mode == 0) {
                *(float2*)&C[(size_t)rr * GN + cc] = make_float2(v0, v1);
                *(float2*)&C[(size_t)(rr + 8) * GN + cc] = make_float2(v2, v3);
            } else {
                const int h = cc >> 6, d = cc & 63;
                const int bb = rr >> 11;
                const int s0 = rr & 2047, s1 = (rr + 8) & 2047;
                const size_t o0 = ((((size_t)bb * H_ + h) * S_ + s0) << 6) + d;
                const size_t o1 = ((((size_t)bb * H_ + h) * S_ + s1) << 6) + d;
                __half* oh = (z == 0) ? op.qh : (z == 1) ? op.kh : op.vh;
                *(uint32_t*)(oh + o0) = rn2(v0, v1);
                *(uint32_t*)(oh + o1) = rn2(v2, v3);
            }
        }
    }
}

// ---------------- f16 flash attention, fixed-shift softmax ------------------
// CTA: 128 threads (4 warps x 16 q-rows = 64 q) x one (b,h); 4 CTAs/SM.
// k-tiles of 64, 3-stage (Kh|Vh 16KB/stage), race-free barrier-first loop.
// P = 2^(s + mask - M); l via all-ones mma. Q pre-scaled by SC2.
#define ATT_STAGE(kt) do {                                                   \
    uint32_t st_ = SST + ((kt) % 3) * 16384;                                 \
    const size_t roff_ = base + (size_t)((kt) * 64) * HD_;                   \
    _Pragma("unroll")                                                        \
    for (int i_ = 0; i_ < 4; i_++) {                                         \
        int idx_ = tid + i_ * 128;                                           \
        int r_ = idx_ >> 3, u_ = idx_ & 7;                                   \
        uint32_t so_ = SW((uint32_t)(r_ * 128 + u_ * 16));                   \
        size_t go_ = roff_ + (size_t)r_ * HD_ + u_ * 8;                      \
        cp16(st_ + so_,        Kh_ + go_);                                   \
        cp16(st_ + 8192 + so_, Vh_ + go_);                                   \
    }                                                                        \
    if (tid < 64)                                                            \
        smaskf[((kt) % 3) * 64 + tid] =                                      \
            (1.0f - mask[b * S_ + (kt) * 64 + tid]) * NEGM2 - MSHIFT;        \
} while (0)

__global__ __launch_bounds__(128) void attn_tc(
    const __half* __restrict__ Qh_, const __half* __restrict__ Kh_,
    const __half* __restrict__ Vh_, const float* __restrict__ mask,
    __half* __restrict__ ctxh)
{
    extern __shared__ char smraw[];
    const uint32_t sb = smem_u32(smraw);
    const uint32_t SQH = sb;                    // Q: 64 x 128B = 8KB
    const uint32_t SST = sb + 8192;             // 3 stages x 16KB
    float* smaskf = (float*)(smraw + 57344);    // 3 x 64 floats

    const int tid = threadIdx.x, lane = tid & 31, wid = tid >> 5;
    const int qt = gridDim.x - 1 - blockIdx.x;  // heavy tiles first
    const int q0 = qt * 64;
    const int bh = blockIdx.y;
    const int b = bh >> 4, hh = bh & 15;
    const size_t base = (size_t)bh * (S_ * HD_);
    const int wq = wid * 16;

    // Q tile: 64 rows x 64 halfs
    {
        const size_t qoff = base + (size_t)q0 * HD_;
#pragma unroll
        for (int i = 0; i < 4; i++) {
            int idx = tid + i * 128;
            int r = idx >> 3, u = idx & 7;
            cp16(SQH + SW((uint32_t)(r * 128 + u * 16)),
                 Qh_ + qoff + (size_t)r * HD_ + u * 8);
        }
    }
    const int ntile = qt + 1;
    ATT_STAGE(0);
    CP_COMMIT();                       // group: Q + stage0
    if (ntile > 1) ATT_STAGE(1);
    CP_COMMIT();                       // group: stage1 (possibly empty)

    const uint32_t arow = (wq + (lane & 15)) * 128 + ((lane >> 4) << 4);
    const uint32_t bno  = ((lane & 7) + ((lane >> 4) << 3)) * 128
                        + (((lane >> 3) & 1) << 4);
    const uint32_t vro  = (((lane >> 3) & 1) * 8 + (lane & 7)) * 128
                        + ((lane >> 4) << 4);
    const int c0  = (lane & 3) * 2;
    const int rg0 = q0 + wq + (lane >> 2);
    const int rg1 = rg0 + 8;

    float o[8][4];
#pragma unroll
    for (int ni = 0; ni < 8; ni++)
#pragma unroll
        for (int r = 0; r < 4; r++) o[ni][r] = 0.0f;
    float lacc[4] = {0.0f, 0.0f, 0.0f, 0.0f};   // row sums via ones-mma

    for (int kt = 0; kt < ntile; kt++) {
        CP_WAIT1();                    // stage kt resident
        __syncthreads();               // readers of buffer (kt+2)%3 done
        if (kt + 2 < ntile) ATT_STAGE(kt + 2);
        CP_COMMIT();

        const int k0 = kt * 64;
        if (k0 <= q0 + wq + 15) {      // warp-granular causal tile skip
            const uint32_t sKh = SST + (kt % 3) * 16384;
            const uint32_t sVh = sKh + 8192;

            float s[8][4];
#pragma unroll
            for (int ni = 0; ni < 8; ni++)
#pragma unroll
                for (int r = 0; r < 4; r++) s[ni][r] = 0.0f;

            // ---- S = Q.K (Q pre-scaled; scores in base-2 units) ----
#pragma unroll
            for (int k16 = 0; k16 < 4; k16++) {
                const uint32_t kb = k16 * 32;
                uint32_t aH[4], kf[4][4];
                ldsm4(aH[0], aH[1], aH[2], aH[3], SQH + SW(arow + kb));
#pragma unroll
                for (int nt = 0; nt < 4; nt++)
                    ldsm4(kf[nt][0], kf[nt][1], kf[nt][2], kf[nt][3],
                          sKh + SW(bno + nt * 2048 + kb));
#pragma unroll
                for (int ni = 0; ni < 8; ni++)
                    mma_f16(s[ni], aH, kf[ni >> 1][(ni & 1) * 2],
                            kf[ni >> 1][(ni & 1) * 2 + 1]);
            }

            // ---- mask(+M shift) add + causal ----
            const float* mrow = smaskf + (kt % 3) * 64;
            const bool needc = (k0 + 63 > q0 + wq);
#pragma unroll
            for (int ni = 0; ni < 8; ni++) {
                const int kg = k0 + ni * 8 + c0;
                const float ma = mrow[ni * 8 + c0];
                const float mb = mrow[ni * 8 + c0 + 1];
                s[ni][0] += ma;
                s[ni][1] += mb;
                s[ni][2] += ma;
                s[ni][3] += mb;
                if (needc) {
                    if (kg > rg0)     s[ni][0] -= 1e10f;
                    if (kg + 1 > rg0) s[ni][1] -= 1e10f;
                    if (kg > rg1)     s[ni][2] -= 1e10f;
                    if (kg + 1 > rg1) s[ni][3] -= 1e10f;
                }
            }

            // ---- P = 2^s; O += rn(P).V; l += rn(P).ones ----
#pragma unroll
            for (int jb = 0; jb < 4; jb++) {
                uint32_t aP[4];
#pragma unroll
                for (int t = 0; t < 2; t++) {
                    const int ti = jb * 2 + t;
                    aP[t * 2 + 0] = rn2(ex2f(s[ti][0]), ex2f(s[ti][1]));
                    aP[t * 2 + 1] = rn2(ex2f(s[ti][2]), ex2f(s[ti][3]));
                }
                uint32_t vf[4][4];
                const uint32_t vbase = vro + jb * 2048;
#pragma unroll
                for (int nt = 0; nt < 4; nt++)
                    ldsm4t(vf[nt], sVh + SW(vbase + nt * 32));
#pragma unroll
                for (int ni = 0; ni < 8; ni++)
                    mma_f16(o[ni], aP, vf[ni >> 1][(ni & 1) * 2],
                            vf[ni >> 1][(ni & 1) * 2 + 1]);
                mma_f16(lacc, aP, ONES2, ONES2);
            }
        }
    }

    // ---- normalize + write ctx rn(f16) in [B,S,D] layout ----
    const float i0 = 1.0f / lacc[0], i1 = 1.0f / lacc[2];
    const size_t row0 = ((size_t)b * S_ + rg0) * D_ + hh * HD_;
    const size_t row1 = ((size_t)b * S_ + rg1) * D_ + hh * HD_;
#pragma unroll
    for (int ni = 0; ni < 8; ni++) {
        const int d = ni * 8 + c0;
        *(uint32_t*)(ctxh + row0 + d) = rn2(o[ni][0] * i0, o[ni][1] * i0);
        *(uint32_t*)(ctxh + row1 + d) = rn2(o[ni][2] * i1, o[ni][3] * i1);
    }
}

// ---------------------------------------------------------------------------
extern "C" void kernel_launch(void* const* d_in, const int* in_sizes, int n_in,
                              void* d_out, int out_size)
{
    const float* X    = (const float*)d_in[0];
    const float* mask = (const float*)d_in[1];
    const float* Wq   = (const float*)d_in[2];
    const float* bq   = (const float*)d_in[3];
    const float* Wk   = (const float*)d_in[4];
    const float* bk   = (const float*)d_in[5];
    const float* Wv   = (const float*)d_in[6];
    const float* bv   = (const float*)d_in[7];
    const float* Wo   = (const float*)d_in[8];
    const float* bo   = (const float*)d_in[9];
    float* out = (float*)d_out;

    __half *pXh, *pWh, *pQh, *pKh, *pVh, *pCh;
    cudaGetSymbolAddress((void**)&pXh, g_Xh);
    cudaGetSymbolAddress((void**)&pWh, g_Wh);
    cudaGetSymbolAddress((void**)&pQh, g_Qh);
    cudaGetSymbolAddress((void**)&pKh, g_Kh);
    cudaGetSymbolAddress((void**)&pVh, g_Vh);
    cudaGetSymbolAddress((void**)&pCh, g_Ch);

    const int GEMM_SMEM = 3 * 32768;                 // 96 KB
    cudaFuncSetAttribute(gemm1p, cudaFuncAttributeMaxDynamicSharedMemorySize,
                         GEMM_SMEM);
    const int ATTN_SMEM = 57344 + 768;               // 56.8 KB -> 4 CTAs/SM
    cudaFuncSetAttribute(attn_tc, cudaFuncAttributeMaxDynamicSharedMemorySize,
                         ATTN_SMEM);

    const size_t WSZ = (size_t)GK * GN;

    rn_f16<<<M_ * GK / 1024, 256>>>(X, pXh);
    WPtrs ws = {{Wq, Wk, Wv, Wo}};
    transpose_w_all<<<dim3(GN / 32, GK / 32, 4), dim3(32, 8)>>>(ws, pWh);

    QKVOut op = {bq, bk, bv, pQh, pKh, pVh};
    gemm1p<<<dim3(GN / 128, M_ / 128, 3), 256, GEMM_SMEM>>>(
        pXh, pWh, op, nullptr, nullptr, 1);

    dim3 ga(S_ / 64, B_ * H_);     // (32, 32) x 128 threads
    attn_tc<<<ga, 128, ATTN_SMEM>>>(pQh, pKh, pVh, mask, pCh);

    gemm1p<<<dim3(GN / 128, M_ / 128, 1), 256, GEMM_SMEM>>>(
        pCh, pWh + 3 * WSZ, op, bo, out, 0);
}

// round 13
// speedup vs baseline: 5.0482x; 1.0421x over previous
#include <cuda_runtime.h>
#include <cuda_fp16.h>
#include <cstdint>

#define B_   2
#define S_   2048
#define D_   1024
#define H_   16
#define HD_  64
#define M_   (B_ * S_)   // 4096
#define GN   D_
#define GK   D_

#define LOG2E  1.4426950408889634f
#define SC2    (0.125f * LOG2E)            // folded into Q projection
#define NEGM2  (-10000.0f * LOG2E)         // pad-mask additive (base-2)
#define MSHIFT 4.0f                        // fixed softmax shift
#define ONES2  0x3C003C00u                 // packed f16 {1, 1}

// ---------------- scratch (__device__ globals; no allocs allowed) ----------
__device__ __half g_Xh[M_ * GK];                     // rn(f16) X [M][K]
__device__ __half g_Wh[4][GK * GN];                  // W q/k/v/o rn(f16) [N][K]
__device__ __half g_Qh[M_ * D_];                     // head layout, pre-scaled
__device__ __half g_Kh[M_ * D_];
__device__ __half g_Vh[M_ * D_];
__device__ __half g_Ch[M_ * D_];                     // ctx rn(f16) [B,S,D]

// ---------------- PTX helpers (sm_80+ only; tcgen05 rejected here) ---------
__device__ __forceinline__ uint32_t smem_u32(const void* p) {
    uint32_t a;
    asm("{ .reg .u64 t; cvta.to.shared.u64 t, %1; cvt.u32.u64 %0, t; }"
        : "=r"(a) : "l"(p));
    return a;
}
#define SW(o) ((o) ^ (((o) >> 3) & 0x70))
__device__ __forceinline__ void cp16(uint32_t d, const void* g) {
    asm volatile("cp.async.cg.shared.global [%0], [%1], 16;" :: "r"(d), "l"(g) : "memory");
}
#define CP_COMMIT() asm volatile("cp.async.commit_group;" ::: "memory")
#define CP_WAIT0()  asm volatile("cp.async.wait_group 0;" ::: "memory")

__device__ __forceinline__ void ldsm4(uint32_t& r0, uint32_t& r1,
                                      uint32_t& r2, uint32_t& r3, uint32_t a) {
    asm volatile("ldmatrix.sync.aligned.m8n8.x4.shared.b16 {%0,%1,%2,%3}, [%4];"
                 : "=r"(r0), "=r"(r1), "=r"(r2), "=r"(r3) : "r"(a));
}
__device__ __forceinline__ void ldsm4t(uint32_t* r, uint32_t a) {
    asm volatile("ldmatrix.sync.aligned.m8n8.x4.trans.shared.b16 {%0,%1,%2,%3}, [%4];"
                 : "=r"(r[0]), "=r"(r[1]), "=r"(r[2]), "=r"(r[3]) : "r"(a));
}
__device__ __forceinline__ void mma_f16(float* c, const uint32_t* a,
                                        uint32_t b0, uint32_t b1) {
    asm volatile(
        "mma.sync.aligned.m16n8k16.row.col.f32.f16.f16.f32 "
        "{%0,%1,%2,%3}, {%4,%5,%6,%7}, {%8,%9}, {%0,%1,%2,%3};"
        : "+f"(c[0]), "+f"(c[1]), "+f"(c[2]), "+f"(c[3])
        : "r"(a[0]), "r"(a[1]), "r"(a[2]), "r"(a[3]), "r"(b0), "r"(b1));
}
__device__ __forceinline__ uint32_t h2u(__half2 h) {
    return *reinterpret_cast<uint32_t*>(&h);
}
__device__ __forceinline__ uint32_t rn2(float v0, float v1) {
    return h2u(__float22half2_rn(make_float2(v0, v1)));
}
__device__ __forceinline__ float ex2f(float x) {
    float y;
    asm("ex2.approx.ftz.f32 %0, %1;" : "=f"(y) : "f"(x));
    return y;
}

// ---------------- conversion kernels ----------------------------------------
__global__ __launch_bounds__(256) void rn_f16(
    const float* __restrict__ in, __half* __restrict__ out)
{
    int i = blockIdx.x * 256 + threadIdx.x;
    float4 v = ((const float4*)in)[i];
    ((uint32_t*)out)[2 * i]     = rn2(v.x, v.y);
    ((uint32_t*)out)[2 * i + 1] = rn2(v.z, v.w);
}

// All four W [K][N] f32 -> rn(f16) transposed [N][K]; blockIdx.z selects W
struct WPtrs { const float* w[4]; };
__global__ __launch_bounds__(256) void transpose_w_all(
    WPtrs ws, __half* __restrict__ whbase)
{
    __shared__ float t[32][33];
    const float* W = ws.w[blockIdx.z];
    __half* wh = whbase + (size_t)blockIdx.z * (GK * GN);
    const int n0 = blockIdx.x * 32, k0 = blockIdx.y * 32;
    const int tx = threadIdx.x, ty = threadIdx.y;   // (32, 8)
#pragma unroll
    for (int i = 0; i < 32; i += 8)
        t[ty + i][tx] = W[(size_t)(k0 + ty + i) * GN + n0 + tx];
    __syncthreads();
#pragma unroll
    for (int i = 0; i < 32; i += 8)
        wh[(size_t)(n0 + ty + i) * GK + k0 + tx] = __float2half_rn(t[tx][ty + i]);
}

// ---------------- f16 single-pass GEMM, 2-stage, correct ordering -----------
// 128x128 CTA tile, 8 warps (32x64), 16 K-chunks of 64, 64KB smem (3 CTA/SM).
// Loop: WAIT0 (own copies of chunk c done; only pending group)
//       -> __syncthreads (publish chunk c CTA-wide; readers of buf (c+1)&1
//          -- i.e. compute(c-1) -- all finished)
//       -> load(c+1)+commit (flies during compute(c))
//       -> compute(c).
// mode 0: fp32 row-major C (bias biasC)
// mode 1: blockIdx.z = 0/1/2 -> Q / K / V rn(f16) head layout (Q pre-scaled)
struct QKVOut {
    const float *bq, *bk, *bv;
    __half *qh, *kh, *vh;
};

#define G_LOAD(c) do {                                                       \
    uint32_t st_ = sb + ((c) & 1) * 32768;                                   \
    _Pragma("unroll")                                                        \
    for (int i_ = 0; i_ < 4; i_++) {                                         \
        int idx_ = tid + i_ * 256;                                           \
        int r_ = idx_ >> 3, u_ = idx_ & 7;                                   \
        uint32_t so_ = SW((uint32_t)(r_ * 128 + u_ * 16));                   \
        cp16(st_ + so_,         Ah + (size_t)(m0 + r_) * GK + (c) * 64 + u_ * 8); \
        cp16(st_ + 16384 + so_, Wh + (size_t)(n0 + r_) * GK + (c) * 64 + u_ * 8); \
    }                                                                        \
} while (0)

__global__ __launch_bounds__(256) void gemm1p(
    const __half* __restrict__ Ah, const __half* __restrict__ Whb, QKVOut op,
    const float* __restrict__ biasC, float* __restrict__ C, int mode)
{
    extern __shared__ char smc[];
    const uint32_t sb = smem_u32(smc);
    const int tid = threadIdx.x, lane = tid & 31, wid = tid >> 5;
    const int m0 = blockIdx.y * 128, n0 = blockIdx.x * 128;
    const int z = blockIdx.z;
    const __half* Wh = Whb + (mode ? (size_t)z * (GK * GN) : 0);
    const int wm = (wid & 3) * 32, wn = (wid >> 2) * 64;

    float acc[2][8][4];
#pragma unroll
    for (int mi = 0; mi < 2; mi++)
#pragma unroll
        for (int ni = 0; ni < 8; ni++)
#pragma unroll
            for (int r = 0; r < 4; r++) acc[mi][ni][r] = 0.0f;

    uint32_t aoff[2], boff[4];
#pragma unroll
    for (int mi = 0; mi < 2; mi++)
        aoff[mi] = (wm + mi * 16 + (lane & 15)) * 128 + ((lane >> 4) << 4);
#pragma unroll
    for (int nt = 0; nt < 4; nt++)
        boff[nt] = (wn + nt * 16 + (lane & 7) + ((lane >> 4) << 3)) * 128
                 + (((lane >> 3) & 1) << 4);

    G_LOAD(0); CP_COMMIT();

    for (int c = 0; c < 16; c++) {
        CP_WAIT0();                    // own copies of chunk c complete
        __syncthreads();               // chunk c visible; buf (c+1)&1 free
        if (c + 1 < 16) {
            G_LOAD(c + 1);
            CP_COMMIT();               // lands during compute(c)
        }

        const uint32_t sA = sb + (c & 1) * 32768;
        const uint32_t sW = sA + 16384;
#pragma unroll
        for (int k16 = 0; k16 < 4; k16++) {
            const uint32_t kb = k16 * 32;
            uint32_t a[2][4], w[4][4];
            ldsm4(a[0][0], a[0][1], a[0][2], a[0][3], sA + SW(aoff[0] + kb));
            ldsm4(a[1][0], a[1][1], a[1][2], a[1][3], sA + SW(aoff[1] + kb));
#pragma unroll
            for (int nt = 0; nt < 4; nt++)
                ldsm4(w[nt][0], w[nt][1], w[nt][2], w[nt][3],
                      sW + SW(boff[nt] + kb));
#pragma unroll
            for (int mi = 0; mi < 2; mi++)
#pragma unroll
                for (int ni = 0; ni < 8; ni++)
                    mma_f16(acc[mi][ni], a[mi],
                            w[ni >> 1][(ni & 1) * 2], w[ni >> 1][(ni & 1) * 2 + 1]);
        }
    }

    // epilogue
    const float* bias = mode ? ((z == 0) ? op.bq : (z == 1) ? op.bk : op.bv)
                             : biasC;
    const float osc = (mode == 1 && z == 0) ? SC2 : 1.0f;  // fold score scale
    const int r0 = lane >> 2, cq = (lane & 3) * 2;
#pragma unroll
    for (int mi = 0; mi < 2; mi++) {
#pragma unroll
        for (int ni = 0; ni < 8; ni++) {
            const int rr = m0 + wm + mi * 16 + r0;
            const int cc = n0 + wn + ni * 8 + cq;
            const float2 bv = *(const float2*)&bias[cc];
            float v0 = (acc[mi][ni][0] + bv.x) * osc;
            float v1 = (acc[mi][ni][1] + bv.y) * osc;
            float v2 = (acc[mi][ni][2] + bv.x) * osc;
            float v3 = (acc[mi][ni][3] + bv.y) * osc;
            if (mode == 0) {
                *(float2*)&C[(size_t)rr * GN + cc] = make_float2(v0, v1);
                *(float2*)&C[(size_t)(rr + 8) * GN + cc] = make_float2(v2, v3);
            } else {
                const int h = cc >> 6, d = cc & 63;
                const int bb = rr >> 11;
                const int s0 = rr & 2047, s1 = (rr + 8) & 2047;
                const size_t o0 = ((((size_t)bb * H_ + h) * S_ + s0) << 6) + d;
                const size_t o1 = ((((size_t)bb * H_ + h) * S_ + s1) << 6) + d;
                __half* oh = (z == 0) ? op.qh : (z == 1) ? op.kh : op.vh;
                *(uint32_t*)(oh + o0) = rn2(v0, v1);
                *(uint32_t*)(oh + o1) = rn2(v2, v3);
            }
        }
    }
}

// ---------------- f16 flash attention, fixed-shift softmax ------------------
// CTA: 128 threads (4 warps x 16 q = 64 q) x (b,h); 40.5KB smem -> 4 CTA/SM.
// 2-stage (Kh|Vh 16KB/stage), WAIT0 -> sync -> prefetch -> compute ordering.
// P = 2^(s + mask - M); l via all-ones mma. Q pre-scaled by SC2.
#define ATT_STAGE(kt) do {                                                   \
    uint32_t st_ = SST + ((kt) & 1) * 16384;                                 \
    const size_t roff_ = base + (size_t)((kt) * 64) * HD_;                   \
    _Pragma("unroll")                                                        \
    for (int i_ = 0; i_ < 4; i_++) {                                         \
        int idx_ = tid + i_ * 128;                                           \
        int r_ = idx_ >> 3, u_ = idx_ & 7;                                   \
        uint32_t so_ = SW((uint32_t)(r_ * 128 + u_ * 16));                   \
        size_t go_ = roff_ + (size_t)r_ * HD_ + u_ * 8;                      \
        cp16(st_ + so_,        Kh_ + go_);                                   \
        cp16(st_ + 8192 + so_, Vh_ + go_);                                   \
    }                                                                        \
    if (tid < 64)                                                            \
        smaskf[((kt) & 1) * 64 + tid] =                                      \
            (1.0f - mask[b * S_ + (kt) * 64 + tid]) * NEGM2 - MSHIFT;        \
} while (0)

__global__ __launch_bounds__(128) void attn_tc(
    const __half* __restrict__ Qh_, const __half* __restrict__ Kh_,
    const __half* __restrict__ Vh_, const float* __restrict__ mask,
    __half* __restrict__ ctxh)
{
    extern __shared__ char smraw[];
    const uint32_t sb = smem_u32(smraw);
    const uint32_t SQH = sb;                    // Q: 64 x 128B = 8KB
    const uint32_t SST = sb + 8192;             // 2 stages x 16KB
    float* smaskf = (float*)(smraw + 40960);    // 2 x 64 floats

    const int tid = threadIdx.x, lane = tid & 31, wid = tid >> 5;
    const int qt = gridDim.x - 1 - blockIdx.x;  // heavy tiles first
    const int q0 = qt * 64;
    const int bh = blockIdx.y;
    const int b = bh >> 4, hh = bh & 15;
    const size_t base = (size_t)bh * (S_ * HD_);
    const int wq = wid * 16;

    // Q tile: 64 rows x 64 halfs (group 0 together with stage 0)
    {
        const size_t qoff = base + (size_t)q0 * HD_;
#pragma unroll
        for (int i = 0; i < 4; i++) {
            int idx = tid + i * 128;
            int r = idx >> 3, u = idx & 7;
            cp16(SQH + SW((uint32_t)(r * 128 + u * 16)),
                 Qh_ + qoff + (size_t)r * HD_ + u * 8);
        }
    }
    const int ntile = qt + 1;
    ATT_STAGE(0);
    CP_COMMIT();

    const uint32_t arow = (wq + (lane & 15)) * 128 + ((lane >> 4) << 4);
    const uint32_t bno  = ((lane & 7) + ((lane >> 4) << 3)) * 128
                        + (((lane >> 3) & 1) << 4);
    const uint32_t vro  = (((lane >> 3) & 1) * 8 + (lane & 7)) * 128
                        + ((lane >> 4) << 4);
    const int c0  = (lane & 3) * 2;
    const int rg0 = q0 + wq + (lane >> 2);
    const int rg1 = rg0 + 8;

    float o[8][4];
#pragma unroll
    for (int ni = 0; ni < 8; ni++)
#pragma unroll
        for (int r = 0; r < 4; r++) o[ni][r] = 0.0f;
    float lacc[4] = {0.0f, 0.0f, 0.0f, 0.0f};   // row sums via ones-mma

    for (int kt = 0; kt < ntile; kt++) {
        CP_WAIT0();                    // own copies of stage kt complete
        __syncthreads();               // stage kt visible; buf (kt+1)&1 free
        if (kt + 1 < ntile) {
            ATT_STAGE(kt + 1);
            CP_COMMIT();               // lands during compute(kt)
        }

        const int k0 = kt * 64;
        if (k0 <= q0 + wq + 15) {      // warp-granular causal tile skip
            const uint32_t sKh = SST + (kt & 1) * 16384;
            const uint32_t sVh = sKh + 8192;

            float s[8][4];
#pragma unroll
            for (int ni = 0; ni < 8; ni++)
#pragma unroll
                for (int r = 0; r < 4; r++) s[ni][r] = 0.0f;

            // ---- S = Q.K (Q pre-scaled; scores in base-2 units) ----
#pragma unroll
            for (int k16 = 0; k16 < 4; k16++) {
                const uint32_t kb = k16 * 32;
                uint32_t aH[4], kf[4][4];
                ldsm4(aH[0], aH[1], aH[2], aH[3], SQH + SW(arow + kb));
#pragma unroll
                for (int nt = 0; nt < 4; nt++)
                    ldsm4(kf[nt][0], kf[nt][1], kf[nt][2], kf[nt][3],
                          sKh + SW(bno + nt * 2048 + kb));
#pragma unroll
                for (int ni = 0; ni < 8; ni++)
                    mma_f16(s[ni], aH, kf[ni >> 1][(ni & 1) * 2],
                            kf[ni >> 1][(ni & 1) * 2 + 1]);
            }

            // ---- mask(+M shift) add + causal ----
            const float* mrow = smaskf + (kt & 1) * 64;
            const bool needc = (k0 + 63 > q0 + wq);
#pragma unroll
            for (int ni = 0; ni < 8; ni++) {
                const int kg = k0 + ni * 8 + c0;
                const float ma = mrow[ni * 8 + c0];
                const float mb = mrow[ni * 8 + c0 + 1];
                s[ni][0] += ma;
                s[ni][1] += mb;
                s[ni][2] += ma;
                s[ni][3] += mb;
                if (needc) {
                    if (kg > rg0)     s[ni][0] -= 1e10f;
                    if (kg + 1 > rg0) s[ni][1] -= 1e10f;
                    if (kg > rg1)     s[ni][2] -= 1e10f;
                    if (kg + 1 > rg1) s[ni][3] -= 1e10f;
                }
            }

            // ---- P = 2^s; O += rn(P).V; l += rn(P).ones ----
#pragma unroll
            for (int jb = 0; jb < 4; jb++) {
                uint32_t aP[4];
#pragma unroll
                for (int t = 0; t < 2; t++) {
                    const int ti = jb * 2 + t;
                    aP[t * 2 + 0] = rn2(ex2f(s[ti][0]), ex2f(s[ti][1]));
                    aP[t * 2 + 1] = rn2(ex2f(s[ti][2]), ex2f(s[ti][3]));
                }
                uint32_t vf[4][4];
                const uint32_t vbase = vro + jb * 2048;
#pragma unroll
                for (int nt = 0; nt < 4; nt++)
                    ldsm4t(vf[nt], sVh + SW(vbase + nt * 32));
#pragma unroll
                for (int ni = 0; ni < 8; ni++)
                    mma_f16(o[ni], aP, vf[ni >> 1][(ni & 1) * 2],
                            vf[ni >> 1][(ni & 1) * 2 + 1]);
                mma_f16(lacc, aP, ONES2, ONES2);
            }
        }
    }

    // ---- normalize + write ctx rn(f16) in [B,S,D] layout ----
    const float i0 = 1.0f / lacc[0], i1 = 1.0f / lacc[2];
    const size_t row0 = ((size_t)b * S_ + rg0) * D_ + hh * HD_;
    const size_t row1 = ((size_t)b * S_ + rg1) * D_ + hh * HD_;
#pragma unroll
    for (int ni = 0; ni < 8; ni++) {
        const int d = ni * 8 + c0;
        *(uint32_t*)(ctxh + row0 + d) = rn2(o[ni][0] * i0, o[ni][1] * i0);
        *(uint32_t*)(ctxh + row1 + d) = rn2(o[ni][2] * i1, o[ni][3] * i1);
    }
}

// ---------------------------------------------------------------------------
extern "C" void kernel_launch(void* const* d_in, const int* in_sizes, int n_in,
                              void* d_out, int out_size)
{
    const float* X    = (const float*)d_in[0];
    const float* mask = (const float*)d_in[1];
    const float* Wq   = (const float*)d_in[2];
    const float* bq   = (const float*)d_in[3];
    const float* Wk   = (const float*)d_in[4];
    const float* bk   = (const float*)d_in[5];
    const float* Wv   = (const float*)d_in[6];
    const float* bv   = (const float*)d_in[7];
    const float* Wo   = (const float*)d_in[8];
    const float* bo   = (const float*)d_in[9];
    float* out = (float*)d_out;

    __half *pXh, *pWh, *pQh, *pKh, *pVh, *pCh;
    cudaGetSymbolAddress((void**)&pXh, g_Xh);
    cudaGetSymbolAddress((void**)&pWh, g_Wh);
    cudaGetSymbolAddress((void**)&pQh, g_Qh);
    cudaGetSymbolAddress((void**)&pKh, g_Kh);
    cudaGetSymbolAddress((void**)&pVh, g_Vh);
    cudaGetSymbolAddress((void**)&pCh, g_Ch);

    const int GEMM_SMEM = 2 * 32768;                 // 64 KB -> 3 CTAs/SM
    cudaFuncSetAttribute(gemm1p, cudaFuncAttributeMaxDynamicSharedMemorySize,
                         GEMM_SMEM);
    const int ATTN_SMEM = 40960 + 512;               // 40.5 KB -> 4 CTAs/SM
    cudaFuncSetAttribute(attn_tc, cudaFuncAttributeMaxDynamicSharedMemorySize,
                         ATTN_SMEM);

    const size_t WSZ = (size_t)GK * GN;

    rn_f16<<<M_ * GK / 1024, 256>>>(X, pXh);
    WPtrs ws = {{Wq, Wk, Wv, Wo}};
    transpose_w_all<<<dim3(GN / 32, GK / 32, 4), dim3(32, 8)>>>(ws, pWh);

    QKVOut op = {bq, bk, bv, pQh, pKh, pVh};
    gemm1p<<<dim3(GN / 128, M_ / 128, 3), 256, GEMM_SMEM>>>(
        pXh, pWh, op, nullptr, nullptr, 1);

    dim3 ga(S_ / 64, B_ * H_);     // (32, 32) x 128 threads
    attn_tc<<<ga, 128, ATTN_SMEM>>>(pQh, pKh, pVh, mask, pCh);

    gemm1p<<<dim3(GN / 128, M_ / 128, 1), 256, GEMM_SMEM>>>(
        pCh, pWh + 3 * WSZ, op, bo, out, 0);
}